// round 3
// baseline (speedup 1.0000x reference)
#include <cuda_runtime.h>
#include <cuda_bf16.h>
#include <cstddef>

// Problem constants
#define BATCH 8
#define SEQ   1024
#define CDIM  768
#define HEADS 24
#define DHEAD 32
#define QKV_N (3*CDIM)          // 2304
#define ROWS  (BATCH*SEQ)       // 8192

typedef unsigned long long ull;
struct __align__(16) ull2 { ull x, y; };

// packed f32x2 helpers (sm_100+ native dual-fp32 pipe)
__device__ __forceinline__ ull pack2(float lo, float hi) {
    ull r; asm("mov.b64 %0,{%1,%2};" : "=l"(r) : "f"(lo), "f"(hi)); return r;
}
__device__ __forceinline__ void unpack2(ull v, float& lo, float& hi) {
    asm("mov.b64 {%0,%1},%2;" : "=f"(lo), "=f"(hi) : "l"(v));
}
#define FMA2(d, a, b) asm("fma.rn.f32x2 %0,%1,%2,%0;" : "+l"(d) : "l"(a), "l"(b))

// Scratch (allocation-free rule: __device__ globals)
__device__ float g_qkv[(size_t)ROWS * QKV_N];   // [B*N, 2304]
__device__ float g_att[(size_t)ROWS * CDIM];    // [B*N, 768]

// ---------------------------------------------------------------------------
// GEMM with bias:  C[m,n] = sum_k A[m,k] * W[n,k] + bias[n]
// 128x128 tile, BK=16, 256 threads, 8x8 per thread as 2x2 blocks of 4x4.
// f32x2 packed accumulation, smem double buffering.
// ---------------------------------------------------------------------------
#define GM 128
#define GN 128
#define GK 16

__global__ __launch_bounds__(256) void gemm_bias_kernel(
    const float* __restrict__ A, const float* __restrict__ W,
    const float* __restrict__ bias, float* __restrict__ C,
    int M, int N, int K)
{
    __shared__ float As[2][GK][GM];   // k-major
    __shared__ float Bs[2][GK][GN];

    const int t  = threadIdx.x;
    const int tx = t & 15;          // 0..15 -> n quad
    const int ty = t >> 4;          // 0..15 -> m quad
    const int m0 = blockIdx.y * GM;
    const int n0 = blockIdx.x * GN;

    const int lrow = t >> 2;        // 0..63 (loader row base, x2 blocks)
    const int lc4  = (t & 3) * 4;   // 0,4,8,12

    // acc2[i][jp]: i = row within 8 (0-3 low block, 4-7 high block),
    // jp = packed col pair: 0,1 -> cols tx*4+{0,1},{2,3}; 2,3 -> 64+tx*4+...
    ull acc2[8][4];
    #pragma unroll
    for (int i = 0; i < 8; i++)
        #pragma unroll
        for (int j = 0; j < 4; j++) acc2[i][j] = 0ull;

    const int nk = K / GK;

    // preload tile 0
    {
        #pragma unroll
        for (int i = 0; i < 2; i++) {
            const int row = lrow + i * 64;
            float4 a = *(const float4*)&A[(size_t)(m0 + row) * K + lc4];
            As[0][lc4 + 0][row] = a.x;
            As[0][lc4 + 1][row] = a.y;
            As[0][lc4 + 2][row] = a.z;
            As[0][lc4 + 3][row] = a.w;
            float4 b = *(const float4*)&W[(size_t)(n0 + row) * K + lc4];
            Bs[0][lc4 + 0][row] = b.x;
            Bs[0][lc4 + 1][row] = b.y;
            Bs[0][lc4 + 2][row] = b.z;
            Bs[0][lc4 + 3][row] = b.w;
        }
    }
    __syncthreads();

    int buf = 0;
    for (int kt = 0; kt < nk; kt++) {
        float4 pa[2], pb[2];
        if (kt + 1 < nk) {
            const int k0n = (kt + 1) * GK;
            #pragma unroll
            for (int i = 0; i < 2; i++) {
                const int row = lrow + i * 64;
                pa[i] = *(const float4*)&A[(size_t)(m0 + row) * K + k0n + lc4];
                pb[i] = *(const float4*)&W[(size_t)(n0 + row) * K + k0n + lc4];
            }
        }

        #pragma unroll
        for (int kk = 0; kk < GK; kk++) {
            float4 a0 = *(const float4*)&As[buf][kk][ty * 4];
            float4 a1 = *(const float4*)&As[buf][kk][64 + ty * 4];
            ull2  b0 = *(const ull2*)&Bs[buf][kk][tx * 4];
            ull2  b1 = *(const ull2*)&Bs[buf][kk][64 + tx * 4];

            ull ap[8];
            ap[0] = pack2(a0.x, a0.x); ap[1] = pack2(a0.y, a0.y);
            ap[2] = pack2(a0.z, a0.z); ap[3] = pack2(a0.w, a0.w);
            ap[4] = pack2(a1.x, a1.x); ap[5] = pack2(a1.y, a1.y);
            ap[6] = pack2(a1.z, a1.z); ap[7] = pack2(a1.w, a1.w);

            #pragma unroll
            for (int i = 0; i < 8; i++) {
                FMA2(acc2[i][0], ap[i], b0.x);
                FMA2(acc2[i][1], ap[i], b0.y);
                FMA2(acc2[i][2], ap[i], b1.x);
                FMA2(acc2[i][3], ap[i], b1.y);
            }
        }

        if (kt + 1 < nk) {
            const int nb = buf ^ 1;
            #pragma unroll
            for (int i = 0; i < 2; i++) {
                const int row = lrow + i * 64;
                As[nb][lc4 + 0][row] = pa[i].x;
                As[nb][lc4 + 1][row] = pa[i].y;
                As[nb][lc4 + 2][row] = pa[i].z;
                As[nb][lc4 + 3][row] = pa[i].w;
                Bs[nb][lc4 + 0][row] = pb[i].x;
                Bs[nb][lc4 + 1][row] = pb[i].y;
                Bs[nb][lc4 + 2][row] = pb[i].z;
                Bs[nb][lc4 + 3][row] = pb[i].w;
            }
        }
        __syncthreads();
        buf ^= 1;
    }

    // epilogue
    float4 bb0 = *(const float4*)&bias[n0 + tx * 4];
    float4 bb1 = *(const float4*)&bias[n0 + 64 + tx * 4];
    #pragma unroll
    for (int i = 0; i < 8; i++) {
        const int m = m0 + ((i < 4) ? (ty * 4 + i) : (64 + ty * 4 + (i - 4)));
        float o0, o1, o2, o3;
        float4 w0, w1;
        unpack2(acc2[i][0], o0, o1); unpack2(acc2[i][1], o2, o3);
        w0.x = o0 + bb0.x; w0.y = o1 + bb0.y; w0.z = o2 + bb0.z; w0.w = o3 + bb0.w;
        unpack2(acc2[i][2], o0, o1); unpack2(acc2[i][3], o2, o3);
        w1.x = o0 + bb1.x; w1.y = o1 + bb1.y; w1.z = o2 + bb1.z; w1.w = o3 + bb1.w;
        *(float4*)&C[(size_t)m * N + n0 + tx * 4]      = w0;
        *(float4*)&C[(size_t)m * N + n0 + 64 + tx * 4] = w1;
    }
}

// ---------------------------------------------------------------------------
// Flash attention, f32x2 packed: one thread per query row.
// No online softmax (|logit| <= ~10 by construction, exp is safe in fp32).
// ---------------------------------------------------------------------------
#define QT 128
#define KT 32
#define KVPAD 36   // 144B row stride: 16B aligned

__global__ __launch_bounds__(128) void attn_kernel(
    const float* __restrict__ qkv,   // [B*N, 2304]
    const float* __restrict__ bias,  // [H, N, N]
    float* __restrict__ out)         // [B*N, 768]
{
    __shared__ float Ks[KT][KVPAD];
    __shared__ float Vs[KT][KVPAD];

    const int b = blockIdx.z;
    const int h = blockIdx.y;
    const int q = blockIdx.x * QT + threadIdx.x;   // 0..1023

    const float scale = 0.17677669529663687f;      // 1/sqrt(32)

    const float* qrow = qkv + ((size_t)(b * SEQ + q)) * QKV_N + h * 96;
    ull qv2[16];
    #pragma unroll
    for (int i = 0; i < 8; i++) {
        float4 v = *(const float4*)(qrow + i * 4);
        qv2[2 * i + 0] = pack2(v.x * scale, v.y * scale);
        qv2[2 * i + 1] = pack2(v.z * scale, v.w * scale);
    }

    const float* brow = bias + ((size_t)h * SEQ + q) * SEQ;

    ull acc2[16];
    #pragma unroll
    for (int i = 0; i < 16; i++) acc2[i] = 0ull;
    float l = 0.0f;

    for (int k0 = 0; k0 < SEQ; k0 += KT) {
        // cooperative K/V tile load: 32 rows x 32 floats each
        {
            const int t = threadIdx.x;
            #pragma unroll
            for (int i = 0; i < 2; i++) {
                const int e  = t + i * 128;    // 0..255
                const int r  = e >> 3;         // 0..31
                const int d4 = (e & 7) * 4;    // 0..28
                const float* src = qkv + ((size_t)(b * SEQ + k0 + r)) * QKV_N + h * 96;
                *(float4*)&Ks[r][d4] = *(const float4*)(src + 32 + d4);
                *(float4*)&Vs[r][d4] = *(const float4*)(src + 64 + d4);
            }
        }
        __syncthreads();

        #pragma unroll 2
        for (int j4 = 0; j4 < KT / 4; j4++) {
            float4 b4 = *(const float4*)&brow[k0 + j4 * 4];
            float bf[4] = {b4.x, b4.y, b4.z, b4.w};
            #pragma unroll
            for (int u = 0; u < 4; u++) {
                const int j = j4 * 4 + u;
                const ull2* kp = (const ull2*)&Ks[j][0];
                ull s2a = 0ull, s2b = 0ull;
                #pragma unroll
                for (int i = 0; i < 8; i++) {
                    ull2 k2 = kp[i];
                    FMA2(s2a, qv2[2 * i + 0], k2.x);
                    FMA2(s2b, qv2[2 * i + 1], k2.y);
                }
                float x0, x1, y0, y1;
                unpack2(s2a, x0, x1);
                unpack2(s2b, y0, y1);
                const float s = (x0 + x1) + (y0 + y1) + bf[u];
                const float p = __expf(s);
                l += p;
                const ull pp = pack2(p, p);
                const ull2* vp = (const ull2*)&Vs[j][0];
                #pragma unroll
                for (int i = 0; i < 8; i++) {
                    ull2 v2 = vp[i];
                    FMA2(acc2[2 * i + 0], pp, v2.x);
                    FMA2(acc2[2 * i + 1], pp, v2.y);
                }
            }
        }
        __syncthreads();
    }

    const float inv = 1.0f / l;
    float* orow = out + ((size_t)(b * SEQ + q)) * CDIM + h * DHEAD;
    #pragma unroll
    for (int i = 0; i < 8; i++) {
        float e0, e1, e2, e3;
        unpack2(acc2[2 * i + 0], e0, e1);
        unpack2(acc2[2 * i + 1], e2, e3);
        float4 o;
        o.x = e0 * inv; o.y = e1 * inv; o.z = e2 * inv; o.w = e3 * inv;
        *(float4*)(orow + i * 4) = o;
    }
}

// ---------------------------------------------------------------------------
extern "C" void kernel_launch(void* const* d_in, const int* in_sizes, int n_in,
                              void* d_out, int out_size)
{
    const float* x      = (const float*)d_in[0];  // [B,N,C]
    const float* relpos = (const float*)d_in[1];  // [H,N,N]
    const float* Wqkv   = (const float*)d_in[2];  // [3C,C]
    const float* bqkv   = (const float*)d_in[3];  // [3C]
    const float* Wproj  = (const float*)d_in[4];  // [C,C]
    const float* bproj  = (const float*)d_in[5];  // [C]
    float* out = (float*)d_out;                   // [B,N,C]

    float *qkv = nullptr, *att = nullptr;
    cudaGetSymbolAddress((void**)&qkv, g_qkv);
    cudaGetSymbolAddress((void**)&att, g_att);

    // 1) QKV projection: [8192,768] @ [2304,768]^T + b -> [8192,2304]
    gemm_bias_kernel<<<dim3(QKV_N / GN, ROWS / GM), 256>>>(
        x, Wqkv, bqkv, qkv, ROWS, QKV_N, CDIM);

    // 2) fused attention -> [8192,768] (head-interleaved, proj-ready)
    attn_kernel<<<dim3(SEQ / QT, HEADS, BATCH), QT>>>(qkv, relpos, att);

    // 3) output projection: [8192,768] @ [768,768]^T + b
    gemm_bias_kernel<<<dim3(CDIM / GN, ROWS / GM), 256>>>(
        att, Wproj, bproj, out, ROWS, CDIM, CDIM);
}

// round 4
// speedup vs baseline: 1.0612x; 1.0612x over previous
#include <cuda_runtime.h>
#include <cuda_bf16.h>
#include <cstddef>

// Problem constants
#define BATCH 8
#define SEQ   1024
#define CDIM  768
#define HEADS 24
#define DHEAD 32
#define QKV_N (3*CDIM)          // 2304
#define ROWS  (BATCH*SEQ)       // 8192

typedef unsigned long long ull;
struct __align__(16) ull2 { ull x, y; };

__device__ __forceinline__ ull pack2(float lo, float hi) {
    ull r; asm("mov.b64 %0,{%1,%2};" : "=l"(r) : "f"(lo), "f"(hi)); return r;
}
__device__ __forceinline__ void unpack2(ull v, float& lo, float& hi) {
    asm("mov.b64 {%0,%1},%2;" : "=f"(lo), "=f"(hi) : "l"(v));
}
#define FMA2(d, a, b) asm("fma.rn.f32x2 %0,%1,%2,%0;" : "+l"(d) : "l"(a), "l"(b))

// Scratch (allocation-free rule: __device__ globals)
__device__ float g_qkv[(size_t)ROWS * QKV_N];   // [B*N, 2304]
__device__ float g_att[(size_t)ROWS * CDIM];    // [B*N, 768]

// ---------------------------------------------------------------------------
// GEMM with bias:  C[m,n] = sum_k A[m,k] * W[n,k] + bias[n]
// 128x128 tile, BK=16, 256 threads, 8x8 per thread (2x2 blocks of 4x4).
// f32x2 FFMA2 with A stored PRE-DUPLICATED in smem -> zero packing MOVs.
// Single-buffered smem, <=128 regs so 2 CTAs/SM.
// ---------------------------------------------------------------------------
#define GM 128
#define GN 128
#define GK 16
#define ASTR 264   // duplicated-A row stride (floats): 2*GM + 8, 16B-aligned

__global__ __launch_bounds__(256, 2) void gemm_bias_kernel(
    const float* __restrict__ A, const float* __restrict__ W,
    const float* __restrict__ bias, float* __restrict__ C,
    int M, int N, int K)
{
    __shared__ float As2[GK][ASTR];   // each A value stored twice: [2m],[2m+1]
    __shared__ float Bs[GK][GN];

    const int t  = threadIdx.x;
    const int tx = t & 15;          // n quad
    const int ty = t >> 4;          // m quad
    const int m0 = blockIdx.y * GM;
    const int n0 = blockIdx.x * GN;

    const int lrow = t >> 2;        // 0..63
    const int lc4  = (t & 3) * 4;   // 0,4,8,12

    ull acc2[8][4];
    #pragma unroll
    for (int i = 0; i < 8; i++)
        #pragma unroll
        for (int j = 0; j < 4; j++) acc2[i][j] = 0ull;

    for (int k0 = 0; k0 < K; k0 += GK) {
        // cooperative load; A written duplicated (float2 of (v,v))
        #pragma unroll
        for (int i = 0; i < 2; i++) {
            const int r = lrow + i * 64;
            float4 a = *(const float4*)&A[(size_t)(m0 + r) * K + k0 + lc4];
            *(float2*)&As2[lc4 + 0][2 * r] = make_float2(a.x, a.x);
            *(float2*)&As2[lc4 + 1][2 * r] = make_float2(a.y, a.y);
            *(float2*)&As2[lc4 + 2][2 * r] = make_float2(a.z, a.z);
            *(float2*)&As2[lc4 + 3][2 * r] = make_float2(a.w, a.w);
            float4 b = *(const float4*)&W[(size_t)(n0 + r) * K + k0 + lc4];
            Bs[lc4 + 0][r] = b.x;
            Bs[lc4 + 1][r] = b.y;
            Bs[lc4 + 2][r] = b.z;
            Bs[lc4 + 3][r] = b.w;
        }
        __syncthreads();

        #pragma unroll
        for (int kk = 0; kk < GK; kk++) {
            // A: duplicated pairs, direct 16B loads (broadcast across lanes)
            ull2 aA = *(const ull2*)&As2[kk][8 * ty];          // (a0,a0),(a1,a1)
            ull2 aB = *(const ull2*)&As2[kk][8 * ty + 4];      // (a2,a2),(a3,a3)
            ull2 aC = *(const ull2*)&As2[kk][128 + 8 * ty];    // high M block
            ull2 aD = *(const ull2*)&As2[kk][132 + 8 * ty];
            // B: natural pairs
            ull2 b0 = *(const ull2*)&Bs[kk][tx * 4];           // (b0,b1),(b2,b3)
            ull2 b1 = *(const ull2*)&Bs[kk][64 + tx * 4];

            ull ap[8] = {aA.x, aA.y, aB.x, aB.y, aC.x, aC.y, aD.x, aD.y};
            #pragma unroll
            for (int i = 0; i < 8; i++) {
                FMA2(acc2[i][0], ap[i], b0.x);
                FMA2(acc2[i][1], ap[i], b0.y);
                FMA2(acc2[i][2], ap[i], b1.x);
                FMA2(acc2[i][3], ap[i], b1.y);
            }
        }
        __syncthreads();
    }

    // epilogue
    float4 bb0 = *(const float4*)&bias[n0 + tx * 4];
    float4 bb1 = *(const float4*)&bias[n0 + 64 + tx * 4];
    #pragma unroll
    for (int i = 0; i < 8; i++) {
        const int m = m0 + ((i < 4) ? (ty * 4 + i) : (64 + ty * 4 + (i - 4)));
        float o0, o1, o2, o3;
        float4 w0, w1;
        unpack2(acc2[i][0], o0, o1); unpack2(acc2[i][1], o2, o3);
        w0.x = o0 + bb0.x; w0.y = o1 + bb0.y; w0.z = o2 + bb0.z; w0.w = o3 + bb0.w;
        unpack2(acc2[i][2], o0, o1); unpack2(acc2[i][3], o2, o3);
        w1.x = o0 + bb1.x; w1.y = o1 + bb1.y; w1.z = o2 + bb1.z; w1.w = o3 + bb1.w;
        *(float4*)&C[(size_t)m * N + n0 + tx * 4]      = w0;
        *(float4*)&C[(size_t)m * N + n0 + 64 + tx * 4] = w1;
    }
}

// ---------------------------------------------------------------------------
// Flash attention, f32x2 packed, bias staged through smem (coalesced).
// One thread per query row; 128 q rows/block; KT=32 key tile.
// ---------------------------------------------------------------------------
#define QT 128
#define KT 32
#define KVPAD 36
#define BSTR 33    // bias smem row stride: per-lane reads conflict-free

__global__ __launch_bounds__(128) void attn_kernel(
    const float* __restrict__ qkv,   // [B*N, 2304]
    const float* __restrict__ bias,  // [H, N, N]
    float* __restrict__ out)         // [B*N, 768]
{
    __shared__ float Ks[KT][KVPAD];
    __shared__ float Vs[KT][KVPAD];
    __shared__ float Bi[QT][BSTR];

    const int t = threadIdx.x;
    const int b = blockIdx.z;
    const int h = blockIdx.y;
    const int q0 = blockIdx.x * QT;
    const int q  = q0 + t;

    const float scale = 0.17677669529663687f;      // 1/sqrt(32)

    const float* qrow = qkv + ((size_t)(b * SEQ + q)) * QKV_N + h * 96;
    ull qv2[16];
    #pragma unroll
    for (int i = 0; i < 8; i++) {
        float4 v = *(const float4*)(qrow + i * 4);
        qv2[2 * i + 0] = pack2(v.x * scale, v.y * scale);
        qv2[2 * i + 1] = pack2(v.z * scale, v.w * scale);
    }

    ull acc2[16];
    #pragma unroll
    for (int i = 0; i < 16; i++) acc2[i] = 0ull;
    float l = 0.0f;

    for (int k0 = 0; k0 < SEQ; k0 += KT) {
        // K/V tile: 32 rows x 32 floats each
        #pragma unroll
        for (int i = 0; i < 2; i++) {
            const int e  = t + i * 128;    // 0..255
            const int r  = e >> 3;         // 0..31
            const int d4 = (e & 7) * 4;    // 0..28
            const float* src = qkv + ((size_t)(b * SEQ + k0 + r)) * QKV_N + h * 96;
            *(float4*)&Ks[r][d4] = *(const float4*)(src + 32 + d4);
            *(float4*)&Vs[r][d4] = *(const float4*)(src + 64 + d4);
        }
        // bias tile: 128 rows x 32 cols, coalesced rows (4 rows/warp-pass)
        {
            const int br = t >> 3;          // 0..15
            const int c4 = (t & 7) * 4;     // 0..28
            #pragma unroll
            for (int p = 0; p < 8; p++) {
                const int r = p * 16 + br;
                float4 bv = *(const float4*)&bias[((size_t)h * SEQ + q0 + r) * SEQ + k0 + c4];
                Bi[r][c4 + 0] = bv.x;
                Bi[r][c4 + 1] = bv.y;
                Bi[r][c4 + 2] = bv.z;
                Bi[r][c4 + 3] = bv.w;
            }
        }
        __syncthreads();

        #pragma unroll 2
        for (int j4 = 0; j4 < KT / 4; j4++) {
            #pragma unroll
            for (int u = 0; u < 4; u++) {
                const int j = j4 * 4 + u;
                const ull2* kp = (const ull2*)&Ks[j][0];
                ull s2a = 0ull, s2b = 0ull;
                #pragma unroll
                for (int i = 0; i < 8; i++) {
                    ull2 k2 = kp[i];
                    FMA2(s2a, qv2[2 * i + 0], k2.x);
                    FMA2(s2b, qv2[2 * i + 1], k2.y);
                }
                float x0, x1, y0, y1;
                unpack2(s2a, x0, x1);
                unpack2(s2b, y0, y1);
                const float s = (x0 + x1) + (y0 + y1) + Bi[t][j];
                const float p = __expf(s);
                l += p;
                const ull pp = pack2(p, p);
                const ull2* vp = (const ull2*)&Vs[j][0];
                #pragma unroll
                for (int i = 0; i < 8; i++) {
                    ull2 v2 = vp[i];
                    FMA2(acc2[2 * i + 0], pp, v2.x);
                    FMA2(acc2[2 * i + 1], pp, v2.y);
                }
            }
        }
        __syncthreads();
    }

    const float inv = 1.0f / l;
    float* orow = out + ((size_t)(b * SEQ + q)) * CDIM + h * DHEAD;
    #pragma unroll
    for (int i = 0; i < 8; i++) {
        float e0, e1, e2, e3;
        unpack2(acc2[2 * i + 0], e0, e1);
        unpack2(acc2[2 * i + 1], e2, e3);
        float4 o;
        o.x = e0 * inv; o.y = e1 * inv; o.z = e2 * inv; o.w = e3 * inv;
        *(float4*)(orow + i * 4) = o;
    }
}

// ---------------------------------------------------------------------------
extern "C" void kernel_launch(void* const* d_in, const int* in_sizes, int n_in,
                              void* d_out, int out_size)
{
    const float* x      = (const float*)d_in[0];  // [B,N,C]
    const float* relpos = (const float*)d_in[1];  // [H,N,N]
    const float* Wqkv   = (const float*)d_in[2];  // [3C,C]
    const float* bqkv   = (const float*)d_in[3];  // [3C]
    const float* Wproj  = (const float*)d_in[4];  // [C,C]
    const float* bproj  = (const float*)d_in[5];  // [C]
    float* out = (float*)d_out;                   // [B,N,C]

    float *qkv = nullptr, *att = nullptr;
    cudaGetSymbolAddress((void**)&qkv, g_qkv);
    cudaGetSymbolAddress((void**)&att, g_att);

    // 1) QKV projection: [8192,768] @ [2304,768]^T + b -> [8192,2304]
    gemm_bias_kernel<<<dim3(QKV_N / GN, ROWS / GM), 256>>>(
        x, Wqkv, bqkv, qkv, ROWS, QKV_N, CDIM);

    // 2) fused attention -> [8192,768] (head-interleaved, proj-ready)
    attn_kernel<<<dim3(SEQ / QT, HEADS, BATCH), QT>>>(qkv, relpos, att);

    // 3) output projection: [8192,768] @ [768,768]^T + b
    gemm_bias_kernel<<<dim3(CDIM / GN, ROWS / GM), 256>>>(
        att, Wproj, bproj, out, ROWS, CDIM, CDIM);
}

// round 5
// speedup vs baseline: 1.4858x; 1.4000x over previous
#include <cuda_runtime.h>
#include <cuda_bf16.h>
#include <cstddef>
#include <cstdint>

// Problem constants
#define BATCH 8
#define SEQ   1024
#define CDIM  768
#define HEADS 24
#define DHEAD 32
#define QKV_N (3*CDIM)          // 2304
#define ROWS  (BATCH*SEQ)       // 8192

typedef unsigned long long ull;
struct __align__(16) ull2 { ull x, y; };

__device__ __forceinline__ ull pack2(float lo, float hi) {
    ull r; asm("mov.b64 %0,{%1,%2};" : "=l"(r) : "f"(lo), "f"(hi)); return r;
}
__device__ __forceinline__ void unpack2(ull v, float& lo, float& hi) {
    asm("mov.b64 {%0,%1},%2;" : "=f"(lo), "=f"(hi) : "l"(v));
}
#define FMA2(d, a, b) asm("fma.rn.f32x2 %0,%1,%2,%0;" : "+l"(d) : "l"(a), "l"(b))

__device__ __forceinline__ uint32_t f2tf(float f) {
    uint32_t u; asm("cvt.rna.tf32.f32 %0,%1;" : "=r"(u) : "f"(f)); return u;
}

// Scratch (allocation-free rule: __device__ globals)
__device__ float g_qkv[(size_t)ROWS * QKV_N];   // [B*N, 2304]
__device__ float g_att[(size_t)ROWS * CDIM];    // [B*N, 768]

// ---------------------------------------------------------------------------
// tf32 tensor-core GEMM with bias: C[m,n] = sum_k A[m,k]*W[n,k] + bias[n]
// Tile 128x128, BK=32, 256 threads (8 warps), warp tile 32x64 (wm 0..3, wn 0..1).
// mma.sync m16n8k8 tf32. smem layout: per row, 16 "pair" float2 slots
// (k, k+4) packed together, slot XOR-swizzled by row for conflict-free LDS.64.
// ---------------------------------------------------------------------------
#define TM 128
#define TN 128
#define TK 32

__global__ __launch_bounds__(256, 2) void gemm_tc_kernel(
    const float* __restrict__ A, const float* __restrict__ W,
    const float* __restrict__ bias, float* __restrict__ C,
    int M, int N, int K)
{
    // [row][slot*2+half] ; row stride 32 uints
    __shared__ uint32_t As[TM][TK];
    __shared__ uint32_t Bs[TN][TK];

    const int t    = threadIdx.x;
    const int lane = t & 31;
    const int wid  = t >> 5;
    const int wm   = wid & 3;          // 0..3 -> 32-row slab
    const int wn   = wid >> 2;         // 0..1 -> 64-col slab
    const int m0   = blockIdx.y * TM;
    const int n0   = blockIdx.x * TN;

    const int mq = lane >> 2;          // 0..7 (fragment row group)
    const int p  = lane & 3;           // fragment k-pair / col pair

    float c[2][8][4];
    #pragma unroll
    for (int i = 0; i < 2; i++)
        #pragma unroll
        for (int j = 0; j < 8; j++)
            #pragma unroll
            for (int r = 0; r < 4; r++) c[i][j][r] = 0.0f;

    for (int kt = 0; kt < K; kt += TK) {
        // ---- cooperative tile load: 128 rows x 8 float4 each for A and W ----
        #pragma unroll
        for (int i = 0; i < 4; i++) {
            const int f  = t + i * 256;     // 0..1023
            const int r  = f >> 3;          // 0..127
            const int c8 = f & 7;           // float4 index within 32 floats
            const int s    = c8 >> 1;       // k-step 0..3
            const int half = c8 & 1;        // low(k) / high(k+4) of pair
            const int xr   = (r & 7) << 1;  // row swizzle

            float4 a = *(const float4*)&A[(size_t)(m0 + r) * K + kt + c8 * 4];
            As[r][(((s << 2) | 0) ^ xr) * 2 + half] = f2tf(a.x);
            As[r][(((s << 2) | 1) ^ xr) * 2 + half] = f2tf(a.y);
            As[r][(((s << 2) | 2) ^ xr) * 2 + half] = f2tf(a.z);
            As[r][(((s << 2) | 3) ^ xr) * 2 + half] = f2tf(a.w);

            float4 b = *(const float4*)&W[(size_t)(n0 + r) * K + kt + c8 * 4];
            Bs[r][(((s << 2) | 0) ^ xr) * 2 + half] = f2tf(b.x);
            Bs[r][(((s << 2) | 1) ^ xr) * 2 + half] = f2tf(b.y);
            Bs[r][(((s << 2) | 2) ^ xr) * 2 + half] = f2tf(b.z);
            Bs[r][(((s << 2) | 3) ^ xr) * 2 + half] = f2tf(b.w);
        }
        __syncthreads();

        #pragma unroll
        for (int s = 0; s < 4; s++) {
            // B fragments: 8 n-tiles of 8 cols
            uint32_t bf[8][2];
            #pragma unroll
            for (int ni = 0; ni < 8; ni++) {
                const int nr = wn * 64 + ni * 8 + mq;        // smem row (n)
                const int slot = ((s << 2) | p) ^ ((nr & 7) << 1);
                uint2 v = *(const uint2*)&Bs[nr][slot * 2];
                bf[ni][0] = v.x; bf[ni][1] = v.y;
            }
            // A fragments: 2 m-tiles of 16 rows
            uint32_t af[2][4];
            #pragma unroll
            for (int mi = 0; mi < 2; mi++) {
                const int r0 = wm * 32 + mi * 16 + mq;
                const int r1 = r0 + 8;
                const int slot0 = ((s << 2) | p) ^ ((r0 & 7) << 1);
                const int slot1 = ((s << 2) | p) ^ ((r1 & 7) << 1);
                uint2 lo = *(const uint2*)&As[r0][slot0 * 2];
                uint2 hi = *(const uint2*)&As[r1][slot1 * 2];
                af[mi][0] = lo.x; af[mi][1] = hi.x;   // a0 (m,k), a1 (m+8,k)
                af[mi][2] = lo.y; af[mi][3] = hi.y;   // a2 (m,k+4), a3 (m+8,k+4)
            }
            #pragma unroll
            for (int mi = 0; mi < 2; mi++)
                #pragma unroll
                for (int ni = 0; ni < 8; ni++) {
                    asm("mma.sync.aligned.m16n8k8.row.col.f32.tf32.tf32.f32 "
                        "{%0,%1,%2,%3},{%4,%5,%6,%7},{%8,%9},{%0,%1,%2,%3};"
                        : "+f"(c[mi][ni][0]), "+f"(c[mi][ni][1]),
                          "+f"(c[mi][ni][2]), "+f"(c[mi][ni][3])
                        : "r"(af[mi][0]), "r"(af[mi][1]),
                          "r"(af[mi][2]), "r"(af[mi][3]),
                          "r"(bf[ni][0]), "r"(bf[ni][1]));
                }
        }
        __syncthreads();
    }

    // ---- epilogue: add bias, write float2 per (mtile, ntile, rowhalf) ----
    #pragma unroll
    for (int ni = 0; ni < 8; ni++) {
        const int n = n0 + wn * 64 + ni * 8 + p * 2;
        const float2 bb = *(const float2*)&bias[n];
        #pragma unroll
        for (int mi = 0; mi < 2; mi++) {
            const int mA = m0 + wm * 32 + mi * 16 + mq;
            float2 w0, w1;
            w0.x = c[mi][ni][0] + bb.x; w0.y = c[mi][ni][1] + bb.y;
            w1.x = c[mi][ni][2] + bb.x; w1.y = c[mi][ni][3] + bb.y;
            *(float2*)&C[(size_t)mA * N + n]       = w0;
            *(float2*)&C[(size_t)(mA + 8) * N + n] = w1;
        }
    }
}

// ---------------------------------------------------------------------------
// Flash attention, f32x2 packed, bias staged through smem (unchanged from R4).
// ---------------------------------------------------------------------------
#define QT 128
#define KT 32
#define KVPAD 36
#define BSTR 33

__global__ __launch_bounds__(128) void attn_kernel(
    const float* __restrict__ qkv,   // [B*N, 2304]
    const float* __restrict__ bias,  // [H, N, N]
    float* __restrict__ out)         // [B*N, 768]
{
    __shared__ float Ks[KT][KVPAD];
    __shared__ float Vs[KT][KVPAD];
    __shared__ float Bi[QT][BSTR];

    const int t = threadIdx.x;
    const int b = blockIdx.z;
    const int h = blockIdx.y;
    const int q0 = blockIdx.x * QT;
    const int q  = q0 + t;

    const float scale = 0.17677669529663687f;      // 1/sqrt(32)

    const float* qrow = qkv + ((size_t)(b * SEQ + q)) * QKV_N + h * 96;
    ull qv2[16];
    #pragma unroll
    for (int i = 0; i < 8; i++) {
        float4 v = *(const float4*)(qrow + i * 4);
        qv2[2 * i + 0] = pack2(v.x * scale, v.y * scale);
        qv2[2 * i + 1] = pack2(v.z * scale, v.w * scale);
    }

    ull acc2[16];
    #pragma unroll
    for (int i = 0; i < 16; i++) acc2[i] = 0ull;
    float l = 0.0f;

    for (int k0 = 0; k0 < SEQ; k0 += KT) {
        #pragma unroll
        for (int i = 0; i < 2; i++) {
            const int e  = t + i * 128;
            const int r  = e >> 3;
            const int d4 = (e & 7) * 4;
            const float* src = qkv + ((size_t)(b * SEQ + k0 + r)) * QKV_N + h * 96;
            *(float4*)&Ks[r][d4] = *(const float4*)(src + 32 + d4);
            *(float4*)&Vs[r][d4] = *(const float4*)(src + 64 + d4);
        }
        {
            const int br = t >> 3;
            const int c4 = (t & 7) * 4;
            #pragma unroll
            for (int pR = 0; pR < 8; pR++) {
                const int r = pR * 16 + br;
                float4 bv = *(const float4*)&bias[((size_t)h * SEQ + q0 + r) * SEQ + k0 + c4];
                Bi[r][c4 + 0] = bv.x;
                Bi[r][c4 + 1] = bv.y;
                Bi[r][c4 + 2] = bv.z;
                Bi[r][c4 + 3] = bv.w;
            }
        }
        __syncthreads();

        #pragma unroll 2
        for (int j4 = 0; j4 < KT / 4; j4++) {
            #pragma unroll
            for (int u = 0; u < 4; u++) {
                const int j = j4 * 4 + u;
                const ull2* kp = (const ull2*)&Ks[j][0];
                ull s2a = 0ull, s2b = 0ull;
                #pragma unroll
                for (int i = 0; i < 8; i++) {
                    ull2 k2 = kp[i];
                    FMA2(s2a, qv2[2 * i + 0], k2.x);
                    FMA2(s2b, qv2[2 * i + 1], k2.y);
                }
                float x0, x1, y0, y1;
                unpack2(s2a, x0, x1);
                unpack2(s2b, y0, y1);
                const float s = (x0 + x1) + (y0 + y1) + Bi[t][j];
                const float pe = __expf(s);
                l += pe;
                const ull pp = pack2(pe, pe);
                const ull2* vp = (const ull2*)&Vs[j][0];
                #pragma unroll
                for (int i = 0; i < 8; i++) {
                    ull2 v2 = vp[i];
                    FMA2(acc2[2 * i + 0], pp, v2.x);
                    FMA2(acc2[2 * i + 1], pp, v2.y);
                }
            }
        }
        __syncthreads();
    }

    const float inv = 1.0f / l;
    float* orow = out + ((size_t)(b * SEQ + q)) * CDIM + h * DHEAD;
    #pragma unroll
    for (int i = 0; i < 8; i++) {
        float e0, e1, e2, e3;
        unpack2(acc2[2 * i + 0], e0, e1);
        unpack2(acc2[2 * i + 1], e2, e3);
        float4 o;
        o.x = e0 * inv; o.y = e1 * inv; o.z = e2 * inv; o.w = e3 * inv;
        *(float4*)(orow + i * 4) = o;
    }
}

// ---------------------------------------------------------------------------
extern "C" void kernel_launch(void* const* d_in, const int* in_sizes, int n_in,
                              void* d_out, int out_size)
{
    const float* x      = (const float*)d_in[0];  // [B,N,C]
    const float* relpos = (const float*)d_in[1];  // [H,N,N]
    const float* Wqkv   = (const float*)d_in[2];  // [3C,C]
    const float* bqkv   = (const float*)d_in[3];  // [3C]
    const float* Wproj  = (const float*)d_in[4];  // [C,C]
    const float* bproj  = (const float*)d_in[5];  // [C]
    float* out = (float*)d_out;                   // [B,N,C]

    float *qkv = nullptr, *att = nullptr;
    cudaGetSymbolAddress((void**)&qkv, g_qkv);
    cudaGetSymbolAddress((void**)&att, g_att);

    // 1) QKV projection: [8192,768] @ [2304,768]^T + b -> [8192,2304]
    gemm_tc_kernel<<<dim3(QKV_N / TN, ROWS / TM), 256>>>(
        x, Wqkv, bqkv, qkv, ROWS, QKV_N, CDIM);

    // 2) fused attention -> [8192,768] (head-interleaved, proj-ready)
    attn_kernel<<<dim3(SEQ / QT, HEADS, BATCH), QT>>>(qkv, relpos, att);

    // 3) output projection: [8192,768] @ [768,768]^T + b
    gemm_tc_kernel<<<dim3(CDIM / TN, ROWS / TM), 256>>>(
        att, Wproj, bproj, out, ROWS, CDIM, CDIM);
}

// round 6
// speedup vs baseline: 1.5644x; 1.0529x over previous
#include <cuda_runtime.h>
#include <cuda_bf16.h>
#include <cstddef>
#include <cstdint>

// Problem constants
#define BATCH 8
#define SEQ   1024
#define CDIM  768
#define HEADS 24
#define DHEAD 32
#define QKV_N (3*CDIM)          // 2304
#define ROWS  (BATCH*SEQ)       // 8192

__device__ __forceinline__ uint32_t f2tf(float f) {
    uint32_t u; asm("cvt.rna.tf32.f32 %0,%1;" : "=r"(u) : "f"(f)); return u;
}

#define MMA_TF32(C0,C1,C2,C3, A0,A1,A2,A3, B0,B1) \
    asm("mma.sync.aligned.m16n8k8.row.col.f32.tf32.tf32.f32 " \
        "{%0,%1,%2,%3},{%4,%5,%6,%7},{%8,%9},{%0,%1,%2,%3};" \
        : "+f"(C0), "+f"(C1), "+f"(C2), "+f"(C3) \
        : "r"(A0), "r"(A1), "r"(A2), "r"(A3), "r"(B0), "r"(B1))

// pair-slot column map: value at logical col x lives at
// slot = (x>>3)*4 + (x&3), half = (x>>2)&1 ; uint index = slot*2+half
__device__ __forceinline__ int cmap(int x) {
    return ((x >> 3) << 3) + ((x & 3) << 1) + ((x >> 2) & 1);
}

// Scratch (allocation-free rule: __device__ globals)
__device__ float g_qkv[(size_t)ROWS * QKV_N];   // [B*N, 2304]
__device__ float g_att[(size_t)ROWS * CDIM];    // [B*N, 768]

// ---------------------------------------------------------------------------
// tf32 tensor-core GEMM with bias (validated R5 kernel, unchanged)
// ---------------------------------------------------------------------------
#define TM 128
#define TN 128
#define TK 32

__global__ __launch_bounds__(256, 2) void gemm_tc_kernel(
    const float* __restrict__ A, const float* __restrict__ W,
    const float* __restrict__ bias, float* __restrict__ C,
    int M, int N, int K)
{
    __shared__ uint32_t As[TM][TK];
    __shared__ uint32_t Bs[TN][TK];

    const int t    = threadIdx.x;
    const int lane = t & 31;
    const int wid  = t >> 5;
    const int wm   = wid & 3;
    const int wn   = wid >> 2;
    const int m0   = blockIdx.y * TM;
    const int n0   = blockIdx.x * TN;

    const int mq = lane >> 2;
    const int p  = lane & 3;

    float c[2][8][4];
    #pragma unroll
    for (int i = 0; i < 2; i++)
        #pragma unroll
        for (int j = 0; j < 8; j++)
            #pragma unroll
            for (int r = 0; r < 4; r++) c[i][j][r] = 0.0f;

    for (int kt = 0; kt < K; kt += TK) {
        #pragma unroll
        for (int i = 0; i < 4; i++) {
            const int f  = t + i * 256;
            const int r  = f >> 3;
            const int c8 = f & 7;
            const int s    = c8 >> 1;
            const int half = c8 & 1;
            const int xr   = (r & 7) << 1;

            float4 a = *(const float4*)&A[(size_t)(m0 + r) * K + kt + c8 * 4];
            As[r][(((s << 2) | 0) ^ xr) * 2 + half] = f2tf(a.x);
            As[r][(((s << 2) | 1) ^ xr) * 2 + half] = f2tf(a.y);
            As[r][(((s << 2) | 2) ^ xr) * 2 + half] = f2tf(a.z);
            As[r][(((s << 2) | 3) ^ xr) * 2 + half] = f2tf(a.w);

            float4 b = *(const float4*)&W[(size_t)(n0 + r) * K + kt + c8 * 4];
            Bs[r][(((s << 2) | 0) ^ xr) * 2 + half] = f2tf(b.x);
            Bs[r][(((s << 2) | 1) ^ xr) * 2 + half] = f2tf(b.y);
            Bs[r][(((s << 2) | 2) ^ xr) * 2 + half] = f2tf(b.z);
            Bs[r][(((s << 2) | 3) ^ xr) * 2 + half] = f2tf(b.w);
        }
        __syncthreads();

        #pragma unroll
        for (int s = 0; s < 4; s++) {
            uint32_t bf[8][2];
            #pragma unroll
            for (int ni = 0; ni < 8; ni++) {
                const int nr = wn * 64 + ni * 8 + mq;
                const int slot = ((s << 2) | p) ^ ((nr & 7) << 1);
                uint2 v = *(const uint2*)&Bs[nr][slot * 2];
                bf[ni][0] = v.x; bf[ni][1] = v.y;
            }
            uint32_t af[2][4];
            #pragma unroll
            for (int mi = 0; mi < 2; mi++) {
                const int r0 = wm * 32 + mi * 16 + mq;
                const int r1 = r0 + 8;
                const int slot0 = ((s << 2) | p) ^ ((r0 & 7) << 1);
                const int slot1 = ((s << 2) | p) ^ ((r1 & 7) << 1);
                uint2 lo = *(const uint2*)&As[r0][slot0 * 2];
                uint2 hi = *(const uint2*)&As[r1][slot1 * 2];
                af[mi][0] = lo.x; af[mi][1] = hi.x;
                af[mi][2] = lo.y; af[mi][3] = hi.y;
            }
            #pragma unroll
            for (int mi = 0; mi < 2; mi++)
                #pragma unroll
                for (int ni = 0; ni < 8; ni++)
                    MMA_TF32(c[mi][ni][0], c[mi][ni][1], c[mi][ni][2], c[mi][ni][3],
                             af[mi][0], af[mi][1], af[mi][2], af[mi][3],
                             bf[ni][0], bf[ni][1]);
        }
        __syncthreads();
    }

    #pragma unroll
    for (int ni = 0; ni < 8; ni++) {
        const int n = n0 + wn * 64 + ni * 8 + p * 2;
        const float2 bb = *(const float2*)&bias[n];
        #pragma unroll
        for (int mi = 0; mi < 2; mi++) {
            const int mA = m0 + wm * 32 + mi * 16 + mq;
            float2 w0, w1;
            w0.x = c[mi][ni][0] + bb.x; w0.y = c[mi][ni][1] + bb.y;
            w1.x = c[mi][ni][2] + bb.x; w1.y = c[mi][ni][3] + bb.y;
            *(float2*)&C[(size_t)mA * N + n]       = w0;
            *(float2*)&C[(size_t)(mA + 8) * N + n] = w1;
        }
    }
}

// ---------------------------------------------------------------------------
// Tensor-core flash attention.
// Block: 128 q rows for one (b,h). 8 warps x 16 q rows. Bc=32 key tile.
// QK^T via 3-mma tf32 error-split (fp32-accurate logits); PV via tf32.
// P staged through warp-private smem rows in A-fragment pair-slot layout.
// ---------------------------------------------------------------------------
#define AQT 128
#define ABC 32
#define KSTR 34   // uint stride: 32 cols + 2 pad (even -> uint2 aligned)

__global__ __launch_bounds__(256, 2) void attn_tc_kernel(
    const float* __restrict__ qkv,   // [B*N, 2304]
    const float* __restrict__ bias,  // [H, N, N]
    float* __restrict__ out)         // [B*N, 768]
{
    __shared__ uint32_t Khi[ABC][KSTR];
    __shared__ uint32_t Klo[ABC][KSTR];
    __shared__ uint32_t Vts[DHEAD][KSTR];   // V transposed: [d][j]
    __shared__ uint32_t Ps[AQT][KSTR];      // P: [q][j] pair-slot

    const int t    = threadIdx.x;
    const int lane = t & 31;
    const int w    = t >> 5;
    const int b    = blockIdx.x >> 3;
    const int qb   = blockIdx.x & 7;
    const int h    = blockIdx.y;
    const int q0   = qb * AQT;
    const int mq   = lane >> 2;
    const int p    = lane & 3;

    const float scale = 0.17677669529663687f;   // 1/sqrt(32)

    const int row_lo = w * 16 + mq;
    const int row_hi = row_lo + 8;

    // ---- Q fragments, hi + residual ----
    uint32_t qh[4][4], ql[4][4];
    {
        const float* Qa = qkv + ((size_t)(b * SEQ + q0 + row_lo)) * QKV_N + h * 96;
        const float* Qb = qkv + ((size_t)(b * SEQ + q0 + row_hi)) * QKV_N + h * 96;
        #pragma unroll
        for (int s = 0; s < 4; s++) {
            float v[4];
            v[0] = Qa[s * 8 + p]     * scale;
            v[1] = Qb[s * 8 + p]     * scale;
            v[2] = Qa[s * 8 + p + 4] * scale;
            v[3] = Qb[s * 8 + p + 4] * scale;
            #pragma unroll
            for (int i = 0; i < 4; i++) {
                uint32_t hi = f2tf(v[i]);
                qh[s][i] = hi;
                ql[s][i] = f2tf(v[i] - __uint_as_float(hi));
            }
        }
    }

    const float* bp_lo = bias + ((size_t)h * SEQ + q0 + row_lo) * SEQ;
    const float* bp_hi = bias + ((size_t)h * SEQ + q0 + row_hi) * SEQ;

    float o[4][4];
    #pragma unroll
    for (int i = 0; i < 4; i++)
        #pragma unroll
        for (int j = 0; j < 4; j++) o[i][j] = 0.0f;
    float l_lo = 0.0f, l_hi = 0.0f;

    for (int kb = 0; kb < SEQ; kb += ABC) {
        __syncthreads();   // prior PV reads done before tile overwrite
        // ---- load K (split) and V^T: 32 rows x 32 floats, 1 float4/thread ----
        {
            const int j = t >> 3;          // 0..31
            const int c = t & 7;           // float4 col
            const float* src = qkv + ((size_t)(b * SEQ + kb + j)) * QKV_N + h * 96;
            float4 kv = *(const float4*)(src + 32 + c * 4);
            float4 vv = *(const float4*)(src + 64 + c * 4);
            const float kf[4] = {kv.x, kv.y, kv.z, kv.w};
            const float vf[4] = {vv.x, vv.y, vv.z, vv.w};
            const int jcol = cmap(j);
            #pragma unroll
            for (int e = 0; e < 4; e++) {
                const int d = c * 4 + e;
                const int dcol = cmap(d);
                uint32_t hi = f2tf(kf[e]);
                Khi[j][dcol] = hi;
                Klo[j][dcol] = f2tf(kf[e] - __uint_as_float(hi));
                Vts[d][jcol] = f2tf(vf[e]);
            }
        }
        __syncthreads();

        // ---- S = Q K^T (3-mma split) ----
        float cf[4][4];
        #pragma unroll
        for (int i = 0; i < 4; i++)
            #pragma unroll
            for (int j = 0; j < 4; j++) cf[i][j] = 0.0f;

        #pragma unroll
        for (int s = 0; s < 4; s++) {
            #pragma unroll
            for (int ni = 0; ni < 4; ni++) {
                const int nr = ni * 8 + mq;
                uint2 bh = *(const uint2*)&Khi[nr][(s * 4 + p) * 2];
                uint2 bl = *(const uint2*)&Klo[nr][(s * 4 + p) * 2];
                MMA_TF32(cf[ni][0], cf[ni][1], cf[ni][2], cf[ni][3],
                         qh[s][0], qh[s][1], qh[s][2], qh[s][3], bh.x, bh.y);
                MMA_TF32(cf[ni][0], cf[ni][1], cf[ni][2], cf[ni][3],
                         ql[s][0], ql[s][1], ql[s][2], ql[s][3], bh.x, bh.y);
                MMA_TF32(cf[ni][0], cf[ni][1], cf[ni][2], cf[ni][3],
                         qh[s][0], qh[s][1], qh[s][2], qh[s][3], bl.x, bl.y);
            }
        }

        // ---- bias + exp + P store + row sums ----
        #pragma unroll
        for (int ni = 0; ni < 4; ni++) {
            const int jj = kb + ni * 8 + 2 * p;
            float2 blo = *(const float2*)(bp_lo + jj);
            float2 bhi = *(const float2*)(bp_hi + jj);
            float p00 = __expf(cf[ni][0] + blo.x);
            float p01 = __expf(cf[ni][1] + blo.y);
            float p10 = __expf(cf[ni][2] + bhi.x);
            float p11 = __expf(cf[ni][3] + bhi.y);
            l_lo += p00 + p01;
            l_hi += p10 + p11;
            const int ja = ni * 8 + 2 * p;
            const int ca = cmap(ja);
            const int cb = cmap(ja + 1);
            Ps[row_lo][ca] = f2tf(p00);
            Ps[row_lo][cb] = f2tf(p01);
            Ps[row_hi][ca] = f2tf(p10);
            Ps[row_hi][cb] = f2tf(p11);
        }
        __syncwarp();   // Ps rows are warp-private

        // ---- O += P V ----
        #pragma unroll
        for (int s2 = 0; s2 < 4; s2++) {
            uint2 alo = *(const uint2*)&Ps[row_lo][(s2 * 4 + p) * 2];
            uint2 ahi = *(const uint2*)&Ps[row_hi][(s2 * 4 + p) * 2];
            #pragma unroll
            for (int nt = 0; nt < 4; nt++) {
                uint2 bv = *(const uint2*)&Vts[nt * 8 + mq][(s2 * 4 + p) * 2];
                MMA_TF32(o[nt][0], o[nt][1], o[nt][2], o[nt][3],
                         alo.x, ahi.x, alo.y, ahi.y, bv.x, bv.y);
            }
        }
    }

    // ---- row-sum reduce across the 4 lanes of each row quad ----
    #pragma unroll
    for (int m = 1; m <= 2; m <<= 1) {
        l_lo += __shfl_xor_sync(0xffffffffu, l_lo, m);
        l_hi += __shfl_xor_sync(0xffffffffu, l_hi, m);
    }
    const float inv_lo = 1.0f / l_lo;
    const float inv_hi = 1.0f / l_hi;

    float* po_lo = out + ((size_t)(b * SEQ + q0 + row_lo)) * CDIM + h * DHEAD;
    float* po_hi = out + ((size_t)(b * SEQ + q0 + row_hi)) * CDIM + h * DHEAD;
    #pragma unroll
    for (int nt = 0; nt < 4; nt++) {
        float2 w0, w1;
        w0.x = o[nt][0] * inv_lo; w0.y = o[nt][1] * inv_lo;
        w1.x = o[nt][2] * inv_hi; w1.y = o[nt][3] * inv_hi;
        *(float2*)(po_lo + nt * 8 + 2 * p) = w0;
        *(float2*)(po_hi + nt * 8 + 2 * p) = w1;
    }
}

// ---------------------------------------------------------------------------
extern "C" void kernel_launch(void* const* d_in, const int* in_sizes, int n_in,
                              void* d_out, int out_size)
{
    const float* x      = (const float*)d_in[0];  // [B,N,C]
    const float* relpos = (const float*)d_in[1];  // [H,N,N]
    const float* Wqkv   = (const float*)d_in[2];  // [3C,C]
    const float* bqkv   = (const float*)d_in[3];  // [3C]
    const float* Wproj  = (const float*)d_in[4];  // [C,C]
    const float* bproj  = (const float*)d_in[5];  // [C]
    float* out = (float*)d_out;                   // [B,N,C]

    float *qkv = nullptr, *att = nullptr;
    cudaGetSymbolAddress((void**)&qkv, g_qkv);
    cudaGetSymbolAddress((void**)&att, g_att);

    // 1) QKV projection
    gemm_tc_kernel<<<dim3(QKV_N / TN, ROWS / TM), 256>>>(
        x, Wqkv, bqkv, qkv, ROWS, QKV_N, CDIM);

    // 2) tensor-core flash attention (h slowest -> bias L2 reuse across batch)
    attn_tc_kernel<<<dim3(BATCH * (SEQ / AQT), HEADS), 256>>>(qkv, relpos, att);

    // 3) output projection
    gemm_tc_kernel<<<dim3(CDIM / TN, ROWS / TM), 256>>>(
        att, Wproj, bproj, out, ROWS, CDIM, CDIM);
}

// round 7
// speedup vs baseline: 1.8255x; 1.1669x over previous
#include <cuda_runtime.h>
#include <cuda_bf16.h>
#include <cstddef>
#include <cstdint>

// Problem constants
#define BATCH 8
#define SEQ   1024
#define CDIM  768
#define HEADS 24
#define DHEAD 32
#define QKV_N (3*CDIM)          // 2304
#define ROWS  (BATCH*SEQ)       // 8192

__device__ __forceinline__ uint32_t f2tf(float f) {
    uint32_t u; asm("cvt.rna.tf32.f32 %0,%1;" : "=r"(u) : "f"(f)); return u;
}

#define MMA_TF32(C0,C1,C2,C3, A0,A1,A2,A3, B0,B1) \
    asm("mma.sync.aligned.m16n8k8.row.col.f32.tf32.tf32.f32 " \
        "{%0,%1,%2,%3},{%4,%5,%6,%7},{%8,%9},{%0,%1,%2,%3};" \
        : "+f"(C0), "+f"(C1), "+f"(C2), "+f"(C3) \
        : "r"(A0), "r"(A1), "r"(A2), "r"(A3), "r"(B0), "r"(B1))

// pair-slot column map: value at logical col x lives at
// slot = (x>>3)*4 + (x&3), half = (x>>2)&1 ; uint index = slot*2+half
__device__ __forceinline__ int cmap(int x) {
    return ((x >> 3) << 3) + ((x & 3) << 1) + ((x >> 2) & 1);
}

// Scratch (allocation-free rule: __device__ globals)
__device__ float g_qkv[(size_t)ROWS * QKV_N];   // [B*N, 2304]
__device__ float g_att[(size_t)ROWS * CDIM];    // [B*N, 768]

// ---------------------------------------------------------------------------
// tf32 tensor-core GEMM with bias, double-buffered.
// 512 threads (16 warps), tile 128x128, TK=32, warp tile 32x32.
// Pipeline: prefetch tile k+1 (gmem->regs) while computing tile k from smem;
// store regs->smem (cvt tf32, paired STS.64) into the alternate buffer.
// ---------------------------------------------------------------------------
#define TM 128
#define TN 128
#define TK 32
#define GEMM_SMEM (2 * (TM + TN) * TK * 4)   // 65536 bytes

__device__ __forceinline__ void store_chunk(uint32_t* rowp, int lc, int xr,
                                            float4 v0, float4 v1)
{
    *(uint2*)&rowp[((((lc << 2) | 0) ^ xr) << 1)] = make_uint2(f2tf(v0.x), f2tf(v1.x));
    *(uint2*)&rowp[((((lc << 2) | 1) ^ xr) << 1)] = make_uint2(f2tf(v0.y), f2tf(v1.y));
    *(uint2*)&rowp[((((lc << 2) | 2) ^ xr) << 1)] = make_uint2(f2tf(v0.z), f2tf(v1.z));
    *(uint2*)&rowp[((((lc << 2) | 3) ^ xr) << 1)] = make_uint2(f2tf(v0.w), f2tf(v1.w));
}

__global__ __launch_bounds__(512) void gemm_tc_kernel(
    const float* __restrict__ A, const float* __restrict__ W,
    const float* __restrict__ bias, float* __restrict__ C,
    int M, int N, int K)
{
    extern __shared__ uint32_t sm[];
    uint32_t* As = sm;                 // [2][TM][TK]
    uint32_t* Bs = sm + 2 * TM * TK;   // [2][TN][TK]

    const int t    = threadIdx.x;
    const int lane = t & 31;
    const int wid  = t >> 5;
    const int wm   = wid & 3;          // 4 m slabs of 32 rows
    const int wn   = wid >> 2;         // 4 n slabs of 32 cols
    const int m0   = blockIdx.y * TM;
    const int n0   = blockIdx.x * TN;
    const int mq   = lane >> 2;
    const int p    = lane & 3;

    const int lr = t >> 2;             // loader row 0..127
    const int lc = t & 3;              // loader 8-col chunk 0..3
    const int xr = (lr & 7) << 1;

    float c[2][4][4];
    #pragma unroll
    for (int i = 0; i < 2; i++)
        #pragma unroll
        for (int j = 0; j < 4; j++)
            #pragma unroll
            for (int r = 0; r < 4; r++) c[i][j][r] = 0.0f;

    const float* pA = &A[(size_t)(m0 + lr) * K + lc * 8];
    const float* pW = &W[(size_t)(n0 + lr) * K + lc * 8];

    float4 a0 = *(const float4*)(pA);
    float4 a1 = *(const float4*)(pA + 4);
    float4 b0 = *(const float4*)(pW);
    float4 b1 = *(const float4*)(pW + 4);

    store_chunk(As + (size_t)lr * TK, lc, xr, a0, a1);
    store_chunk(Bs + (size_t)lr * TK, lc, xr, b0, b1);
    __syncthreads();

    const int nk = K / TK;
    int buf = 0;
    for (int kt = 0; kt < nk; kt++) {
        const bool more = (kt + 1 < nk);
        if (more) {
            const int ko = (kt + 1) * TK;
            a0 = *(const float4*)(pA + ko);
            a1 = *(const float4*)(pA + ko + 4);
            b0 = *(const float4*)(pW + ko);
            b1 = *(const float4*)(pW + ko + 4);
        }

        const uint32_t* Ab = As + (size_t)buf * TM * TK;
        const uint32_t* Bb = Bs + (size_t)buf * TN * TK;
        #pragma unroll
        for (int s = 0; s < 4; s++) {
            uint32_t bf[4][2];
            #pragma unroll
            for (int ni = 0; ni < 4; ni++) {
                const int nr = wn * 32 + ni * 8 + mq;
                const int slot = ((s << 2) | p) ^ ((nr & 7) << 1);
                uint2 v = *(const uint2*)&Bb[nr * TK + slot * 2];
                bf[ni][0] = v.x; bf[ni][1] = v.y;
            }
            uint32_t af[2][4];
            #pragma unroll
            for (int mi = 0; mi < 2; mi++) {
                const int r0 = wm * 32 + mi * 16 + mq;
                const int r1 = r0 + 8;
                const int slot0 = ((s << 2) | p) ^ ((r0 & 7) << 1);
                const int slot1 = ((s << 2) | p) ^ ((r1 & 7) << 1);
                uint2 lo = *(const uint2*)&Ab[r0 * TK + slot0 * 2];
                uint2 hi = *(const uint2*)&Ab[r1 * TK + slot1 * 2];
                af[mi][0] = lo.x; af[mi][1] = hi.x;
                af[mi][2] = lo.y; af[mi][3] = hi.y;
            }
            #pragma unroll
            for (int mi = 0; mi < 2; mi++)
                #pragma unroll
                for (int ni = 0; ni < 4; ni++)
                    MMA_TF32(c[mi][ni][0], c[mi][ni][1], c[mi][ni][2], c[mi][ni][3],
                             af[mi][0], af[mi][1], af[mi][2], af[mi][3],
                             bf[ni][0], bf[ni][1]);
        }

        if (more) {
            uint32_t* An = As + (size_t)(buf ^ 1) * TM * TK;
            uint32_t* Bn = Bs + (size_t)(buf ^ 1) * TN * TK;
            store_chunk(An + (size_t)lr * TK, lc, xr, a0, a1);
            store_chunk(Bn + (size_t)lr * TK, lc, xr, b0, b1);
        }
        __syncthreads();
        buf ^= 1;
    }

    #pragma unroll
    for (int ni = 0; ni < 4; ni++) {
        const int n = n0 + wn * 32 + ni * 8 + p * 2;
        const float2 bb = *(const float2*)&bias[n];
        #pragma unroll
        for (int mi = 0; mi < 2; mi++) {
            const int mA = m0 + wm * 32 + mi * 16 + mq;
            float2 w0, w1;
            w0.x = c[mi][ni][0] + bb.x; w0.y = c[mi][ni][1] + bb.y;
            w1.x = c[mi][ni][2] + bb.x; w1.y = c[mi][ni][3] + bb.y;
            *(float2*)&C[(size_t)mA * N + n]       = w0;
            *(float2*)&C[(size_t)(mA + 8) * N + n] = w1;
        }
    }
}

// ---------------------------------------------------------------------------
// Tensor-core flash attention.
// 2-term QK split (Q=hi+lo exact, K single rna-tf32). K/V reg-prefetch.
// ---------------------------------------------------------------------------
#define AQT 128
#define ABC 32
#define KSTR 34

__global__ __launch_bounds__(256, 2) void attn_tc_kernel(
    const float* __restrict__ qkv,   // [B*N, 2304]
    const float* __restrict__ bias,  // [H, N, N]
    float* __restrict__ out)         // [B*N, 768]
{
    __shared__ uint32_t Ks[ABC][KSTR];
    __shared__ uint32_t Vts[DHEAD][KSTR];   // V transposed: [d][j]
    __shared__ uint32_t Ps[AQT][KSTR];      // P: [q][j] pair-slot

    const int t    = threadIdx.x;
    const int lane = t & 31;
    const int w    = t >> 5;
    const int b    = blockIdx.x >> 3;
    const int qb   = blockIdx.x & 7;
    const int h    = blockIdx.y;
    const int q0   = qb * AQT;
    const int mq   = lane >> 2;
    const int p    = lane & 3;

    const float scale = 0.17677669529663687f;   // 1/sqrt(32)

    const int row_lo = w * 16 + mq;
    const int row_hi = row_lo + 8;

    // K/V loader indices + prefetch of first tile
    const int jL = t >> 3;          // key row 0..31
    const int cL = t & 7;           // float4 col
    const float* kv0 = qkv + ((size_t)(b * SEQ + jL)) * QKV_N + h * 96;
    float4 kv = *(const float4*)(kv0 + 32 + cL * 4);
    float4 vv = *(const float4*)(kv0 + 64 + cL * 4);

    // ---- Q fragments, hi + residual ----
    uint32_t qh[4][4], ql[4][4];
    {
        const float* Qa = qkv + ((size_t)(b * SEQ + q0 + row_lo)) * QKV_N + h * 96;
        const float* Qb = qkv + ((size_t)(b * SEQ + q0 + row_hi)) * QKV_N + h * 96;
        #pragma unroll
        for (int s = 0; s < 4; s++) {
            float v[4];
            v[0] = Qa[s * 8 + p]     * scale;
            v[1] = Qb[s * 8 + p]     * scale;
            v[2] = Qa[s * 8 + p + 4] * scale;
            v[3] = Qb[s * 8 + p + 4] * scale;
            #pragma unroll
            for (int i = 0; i < 4; i++) {
                uint32_t hi = f2tf(v[i]);
                qh[s][i] = hi;
                ql[s][i] = f2tf(v[i] - __uint_as_float(hi));
            }
        }
    }

    const float* bp_lo = bias + ((size_t)h * SEQ + q0 + row_lo) * SEQ;
    const float* bp_hi = bias + ((size_t)h * SEQ + q0 + row_hi) * SEQ;

    float o[4][4];
    #pragma unroll
    for (int i = 0; i < 4; i++)
        #pragma unroll
        for (int j = 0; j < 4; j++) o[i][j] = 0.0f;
    float l_lo = 0.0f, l_hi = 0.0f;

    for (int kb = 0; kb < SEQ; kb += ABC) {
        __syncthreads();   // prior tile consumers done
        // ---- store prefetched K (rna tf32) and V^T ----
        {
            const float kf[4] = {kv.x, kv.y, kv.z, kv.w};
            const float vf[4] = {vv.x, vv.y, vv.z, vv.w};
            const int jcol = cmap(jL);
            #pragma unroll
            for (int e = 0; e < 4; e++) {
                const int d = cL * 4 + e;
                Ks[jL][cmap(d)] = f2tf(kf[e]);
                Vts[d][jcol]    = f2tf(vf[e]);
            }
        }
        __syncthreads();

        // ---- prefetch next K/V tile into regs (latency hidden by mma) ----
        if (kb + ABC < SEQ) {
            const float* nb = qkv + ((size_t)(b * SEQ + kb + ABC + jL)) * QKV_N + h * 96;
            kv = *(const float4*)(nb + 32 + cL * 4);
            vv = *(const float4*)(nb + 64 + cL * 4);
        }
        // ---- prefetch bias into regs ----
        float2 blo2[4], bhi2[4];
        #pragma unroll
        for (int ni = 0; ni < 4; ni++) {
            blo2[ni] = *(const float2*)(bp_lo + kb + ni * 8 + 2 * p);
            bhi2[ni] = *(const float2*)(bp_hi + kb + ni * 8 + 2 * p);
        }

        // ---- S = Q K^T (2-term split) ----
        float cf[4][4];
        #pragma unroll
        for (int i = 0; i < 4; i++)
            #pragma unroll
            for (int j = 0; j < 4; j++) cf[i][j] = 0.0f;

        #pragma unroll
        for (int s = 0; s < 4; s++) {
            #pragma unroll
            for (int ni = 0; ni < 4; ni++) {
                const int nr = ni * 8 + mq;
                uint2 bh = *(const uint2*)&Ks[nr][(s * 4 + p) * 2];
                MMA_TF32(cf[ni][0], cf[ni][1], cf[ni][2], cf[ni][3],
                         qh[s][0], qh[s][1], qh[s][2], qh[s][3], bh.x, bh.y);
                MMA_TF32(cf[ni][0], cf[ni][1], cf[ni][2], cf[ni][3],
                         ql[s][0], ql[s][1], ql[s][2], ql[s][3], bh.x, bh.y);
            }
        }

        // ---- bias + exp + P store + row sums ----
        #pragma unroll
        for (int ni = 0; ni < 4; ni++) {
            float p00 = __expf(cf[ni][0] + blo2[ni].x);
            float p01 = __expf(cf[ni][1] + blo2[ni].y);
            float p10 = __expf(cf[ni][2] + bhi2[ni].x);
            float p11 = __expf(cf[ni][3] + bhi2[ni].y);
            l_lo += p00 + p01;
            l_hi += p10 + p11;
            const int ja = ni * 8 + 2 * p;
            const int ca = cmap(ja);
            const int cb = cmap(ja + 1);
            Ps[row_lo][ca] = f2tf(p00);
            Ps[row_lo][cb] = f2tf(p01);
            Ps[row_hi][ca] = f2tf(p10);
            Ps[row_hi][cb] = f2tf(p11);
        }
        __syncwarp();   // Ps rows are warp-private

        // ---- O += P V ----
        #pragma unroll
        for (int s2 = 0; s2 < 4; s2++) {
            uint2 alo = *(const uint2*)&Ps[row_lo][(s2 * 4 + p) * 2];
            uint2 ahi = *(const uint2*)&Ps[row_hi][(s2 * 4 + p) * 2];
            #pragma unroll
            for (int nt = 0; nt < 4; nt++) {
                uint2 bv = *(const uint2*)&Vts[nt * 8 + mq][(s2 * 4 + p) * 2];
                MMA_TF32(o[nt][0], o[nt][1], o[nt][2], o[nt][3],
                         alo.x, ahi.x, alo.y, ahi.y, bv.x, bv.y);
            }
        }
    }

    // ---- row-sum reduce across the 4 lanes of each row quad ----
    #pragma unroll
    for (int m = 1; m <= 2; m <<= 1) {
        l_lo += __shfl_xor_sync(0xffffffffu, l_lo, m);
        l_hi += __shfl_xor_sync(0xffffffffu, l_hi, m);
    }
    const float inv_lo = 1.0f / l_lo;
    const float inv_hi = 1.0f / l_hi;

    float* po_lo = out + ((size_t)(b * SEQ + q0 + row_lo)) * CDIM + h * DHEAD;
    float* po_hi = out + ((size_t)(b * SEQ + q0 + row_hi)) * CDIM + h * DHEAD;
    #pragma unroll
    for (int nt = 0; nt < 4; nt++) {
        float2 w0, w1;
        w0.x = o[nt][0] * inv_lo; w0.y = o[nt][1] * inv_lo;
        w1.x = o[nt][2] * inv_hi; w1.y = o[nt][3] * inv_hi;
        *(float2*)(po_lo + nt * 8 + 2 * p) = w0;
        *(float2*)(po_hi + nt * 8 + 2 * p) = w1;
    }
}

// ---------------------------------------------------------------------------
extern "C" void kernel_launch(void* const* d_in, const int* in_sizes, int n_in,
                              void* d_out, int out_size)
{
    const float* x      = (const float*)d_in[0];  // [B,N,C]
    const float* relpos = (const float*)d_in[1];  // [H,N,N]
    const float* Wqkv   = (const float*)d_in[2];  // [3C,C]
    const float* bqkv   = (const float*)d_in[3];  // [3C]
    const float* Wproj  = (const float*)d_in[4];  // [C,C]
    const float* bproj  = (const float*)d_in[5];  // [C]
    float* out = (float*)d_out;                   // [B,N,C]

    float *qkv = nullptr, *att = nullptr;
    cudaGetSymbolAddress((void**)&qkv, g_qkv);
    cudaGetSymbolAddress((void**)&att, g_att);

    cudaFuncSetAttribute(gemm_tc_kernel,
                         cudaFuncAttributeMaxDynamicSharedMemorySize, GEMM_SMEM);

    // 1) QKV projection
    gemm_tc_kernel<<<dim3(QKV_N / TN, ROWS / TM), 512, GEMM_SMEM>>>(
        x, Wqkv, bqkv, qkv, ROWS, QKV_N, CDIM);

    // 2) tensor-core flash attention
    attn_tc_kernel<<<dim3(BATCH * (SEQ / AQT), HEADS), 256>>>(qkv, relpos, att);

    // 3) output projection
    gemm_tc_kernel<<<dim3(CDIM / TN, ROWS / TM), 512, GEMM_SMEM>>>(
        att, Wproj, bproj, out, ROWS, CDIM, CDIM);
}

// round 9
// speedup vs baseline: 2.3560x; 1.2906x over previous
#include <cuda_runtime.h>
#include <cuda_bf16.h>
#include <cstddef>
#include <cstdint>

// Problem constants
#define BATCH 8
#define SEQ   1024
#define CDIM  768
#define HEADS 24
#define DHEAD 32
#define QKV_N (3*CDIM)          // 2304
#define ROWS  (BATCH*SEQ)       // 8192

__device__ __forceinline__ uint32_t f2tf(float f) {
    uint32_t u; asm("cvt.rna.tf32.f32 %0,%1;" : "=r"(u) : "f"(f)); return u;
}

// RNA-to-tf32 via bit bump: HMMA truncates low 13 bits, so +0x1000 makes that
// truncation round-to-nearest (ties away). Sign-magnitude fp32 -> works for
// both signs, carries into exponent correctly.
__device__ __forceinline__ uint32_t rna(uint32_t u) { return u + 0x1000u; }

#define MMA_TF32(C0,C1,C2,C3, A0,A1,A2,A3, B0,B1) \
    asm("mma.sync.aligned.m16n8k8.row.col.f32.tf32.tf32.f32 " \
        "{%0,%1,%2,%3},{%4,%5,%6,%7},{%8,%9},{%0,%1,%2,%3};" \
        : "+f"(C0), "+f"(C1), "+f"(C2), "+f"(C3) \
        : "r"(A0), "r"(A1), "r"(A2), "r"(A3), "r"(B0), "r"(B1))

__device__ __forceinline__ void ldsm4(uint32_t& r0, uint32_t& r1,
                                      uint32_t& r2, uint32_t& r3, uint32_t addr) {
    asm volatile("ldmatrix.sync.aligned.m8n8.x4.shared.b16 {%0,%1,%2,%3},[%4];"
                 : "=r"(r0), "=r"(r1), "=r"(r2), "=r"(r3) : "r"(addr));
}

#define CP_ASYNC16(dst, src) \
    asm volatile("cp.async.cg.shared.global [%0],[%1],16;" :: "r"(dst), "l"(src))
#define CP_COMMIT() asm volatile("cp.async.commit_group;")
#define CP_WAIT0()  asm volatile("cp.async.wait_group 0;")

// pair-slot column map (attention kernel layout)
__device__ __forceinline__ int cmap(int x) {
    return ((x >> 3) << 3) + ((x & 3) << 1) + ((x >> 2) & 1);
}

// Scratch (allocation-free rule: __device__ globals)
__device__ float g_qkv[(size_t)ROWS * QKV_N];   // [B*N, 2304]
__device__ float g_att[(size_t)ROWS * CDIM];    // [B*N, 768]

// ---------------------------------------------------------------------------
// tf32 tensor-core GEMM with bias.
// 256 threads (8 warps), tile 128x128, TK=32, warp tile 32x64.
// cp.async double-buffer, linear 128B rows with 16B-chunk XOR swizzle,
// ldmatrix fragment loads, in-register RNA bump before mma.
// ---------------------------------------------------------------------------
#define TM 128
#define TN 128
#define TK 32
#define TILE_B (TM * TK * 4)          // 16 KB per tile buffer
#define GEMM_SMEM (4 * TILE_B)        // A0 A1 B0 B1

__global__ __launch_bounds__(256, 2) void gemm_tc_kernel(
    const float* __restrict__ A, const float* __restrict__ W,
    const float* __restrict__ bias, float* __restrict__ C,
    int M, int N, int K)
{
    extern __shared__ char smem_raw[];
    const uint32_t sb  = (uint32_t)__cvta_generic_to_shared(smem_raw);
    const uint32_t Ab0 = sb;
    const uint32_t Bb0 = sb + 2 * TILE_B;

    const int t    = threadIdx.x;
    const int lane = t & 31;
    const int wid  = t >> 5;
    const int wm   = wid & 3;           // 4 slabs of 32 rows
    const int wn   = wid >> 2;          // 2 slabs of 64 cols
    const int m0   = blockIdx.y * TM;
    const int n0   = blockIdx.x * TN;
    const int mq   = lane >> 2;
    const int p    = lane & 3;

    // ldmatrix per-lane row/half assignment
    const int rA    = wm * 32 + ((lane >> 3) & 1) * 8 + (lane & 7);
    const int halfA = (lane >> 4) & 1;
    const int xa    = rA & 7;
    const int rB    = wn * 64 + ((lane >> 4) & 1) * 8 + (lane & 7);
    const int halfB = (lane >> 3) & 1;
    const int xb    = rB & 7;

    // loader: 4 A-chunks + 4 B-chunks of 16B per thread per tile
    const int lr = t >> 3;              // base row 0..31, step +32
    const int lc = t & 7;               // chunk col 0..7

    float c[2][8][4];
    #pragma unroll
    for (int i = 0; i < 2; i++)
        #pragma unroll
        for (int j = 0; j < 8; j++)
            #pragma unroll
            for (int r = 0; r < 4; r++) c[i][j][r] = 0.0f;

    const int nk = K / TK;

    // ---- prologue: stage tile 0 ----
    #pragma unroll
    for (int i = 0; i < 4; i++) {
        const int r = lr + i * 32;
        const uint32_t sw = (uint32_t)((lc ^ (r & 7)) * 16);
        CP_ASYNC16(Ab0 + r * 128 + sw, (const char*)&A[(size_t)(m0 + r) * K + lc * 4]);
        CP_ASYNC16(Bb0 + r * 128 + sw, (const char*)&W[(size_t)(n0 + r) * K + lc * 4]);
    }
    CP_COMMIT();
    CP_WAIT0();
    __syncthreads();

    int buf = 0;
    for (int kt = 0; kt < nk; kt++) {
        const bool more = (kt + 1 < nk);
        if (more) {
            const int ko = (kt + 1) * TK;
            const uint32_t Ad = Ab0 + (buf ^ 1) * TILE_B;
            const uint32_t Bd = Bb0 + (buf ^ 1) * TILE_B;
            #pragma unroll
            for (int i = 0; i < 4; i++) {
                const int r = lr + i * 32;
                const uint32_t sw = (uint32_t)((lc ^ (r & 7)) * 16);
                CP_ASYNC16(Ad + r * 128 + sw, (const char*)&A[(size_t)(m0 + r) * K + ko + lc * 4]);
                CP_ASYNC16(Bd + r * 128 + sw, (const char*)&W[(size_t)(n0 + r) * K + ko + lc * 4]);
            }
            CP_COMMIT();
        }

        // ---- compute current buffer ----
        const uint32_t Abase = Ab0 + buf * TILE_B;
        const uint32_t Bbase = Bb0 + buf * TILE_B;
        #pragma unroll
        for (int s = 0; s < 4; s++) {
            uint32_t af[2][4];
            #pragma unroll
            for (int mi = 0; mi < 2; mi++) {
                ldsm4(af[mi][0], af[mi][1], af[mi][2], af[mi][3],
                      Abase + (rA + mi * 16) * 128 + ((uint32_t)(((2 * s + halfA) ^ xa) << 4)));
                af[mi][0] = rna(af[mi][0]); af[mi][1] = rna(af[mi][1]);
                af[mi][2] = rna(af[mi][2]); af[mi][3] = rna(af[mi][3]);
            }
            uint32_t bf[8][2];
            #pragma unroll
            for (int g = 0; g < 4; g++) {
                uint32_t r0, r1, r2, r3;
                ldsm4(r0, r1, r2, r3,
                      Bbase + (rB + g * 16) * 128 + ((uint32_t)(((2 * s + halfB) ^ xb) << 4)));
                bf[2 * g][0] = rna(r0); bf[2 * g][1] = rna(r1);
                bf[2 * g + 1][0] = rna(r2); bf[2 * g + 1][1] = rna(r3);
            }
            #pragma unroll
            for (int mi = 0; mi < 2; mi++)
                #pragma unroll
                for (int ni = 0; ni < 8; ni++)
                    MMA_TF32(c[mi][ni][0], c[mi][ni][1], c[mi][ni][2], c[mi][ni][3],
                             af[mi][0], af[mi][1], af[mi][2], af[mi][3],
                             bf[ni][0], bf[ni][1]);
        }

        if (more) CP_WAIT0();
        __syncthreads();
        buf ^= 1;
    }

    // ---- epilogue ----
    #pragma unroll
    for (int ni = 0; ni < 8; ni++) {
        const int n = n0 + wn * 64 + ni * 8 + p * 2;
        const float2 bb = *(const float2*)&bias[n];
        #pragma unroll
        for (int mi = 0; mi < 2; mi++) {
            const int mA = m0 + wm * 32 + mi * 16 + mq;
            float2 w0, w1;
            w0.x = c[mi][ni][0] + bb.x; w0.y = c[mi][ni][1] + bb.y;
            w1.x = c[mi][ni][2] + bb.x; w1.y = c[mi][ni][3] + bb.y;
            *(float2*)&C[(size_t)mA * N + n]       = w0;
            *(float2*)&C[(size_t)(mA + 8) * N + n] = w1;
        }
    }
}

// ---------------------------------------------------------------------------
// Tensor-core flash attention (unchanged from R7 — validated).
// 2-term QK split (Q=hi+lo exact, K single rna-tf32). K/V reg-prefetch.
// ---------------------------------------------------------------------------
#define AQT 128
#define ABC 32
#define KSTR 34

__global__ __launch_bounds__(256, 2) void attn_tc_kernel(
    const float* __restrict__ qkv,   // [B*N, 2304]
    const float* __restrict__ bias,  // [H, N, N]
    float* __restrict__ out)         // [B*N, 768]
{
    __shared__ uint32_t Ks[ABC][KSTR];
    __shared__ uint32_t Vts[DHEAD][KSTR];   // V transposed: [d][j]
    __shared__ uint32_t Ps[AQT][KSTR];      // P: [q][j] pair-slot

    const int t    = threadIdx.x;
    const int lane = t & 31;
    const int w    = t >> 5;
    const int b    = blockIdx.x >> 3;
    const int qb   = blockIdx.x & 7;
    const int h    = blockIdx.y;
    const int q0   = qb * AQT;
    const int mq   = lane >> 2;
    const int p    = lane & 3;

    const float scale = 0.17677669529663687f;   // 1/sqrt(32)

    const int row_lo = w * 16 + mq;
    const int row_hi = row_lo + 8;

    const int jL = t >> 3;
    const int cL = t & 7;
    const float* kv0 = qkv + ((size_t)(b * SEQ + jL)) * QKV_N + h * 96;
    float4 kv = *(const float4*)(kv0 + 32 + cL * 4);
    float4 vv = *(const float4*)(kv0 + 64 + cL * 4);

    uint32_t qh[4][4], ql[4][4];
    {
        const float* Qa = qkv + ((size_t)(b * SEQ + q0 + row_lo)) * QKV_N + h * 96;
        const float* Qb = qkv + ((size_t)(b * SEQ + q0 + row_hi)) * QKV_N + h * 96;
        #pragma unroll
        for (int s = 0; s < 4; s++) {
            float v[4];
            v[0] = Qa[s * 8 + p]     * scale;
            v[1] = Qb[s * 8 + p]     * scale;
            v[2] = Qa[s * 8 + p + 4] * scale;
            v[3] = Qb[s * 8 + p + 4] * scale;
            #pragma unroll
            for (int i = 0; i < 4; i++) {
                uint32_t hi = f2tf(v[i]);
                qh[s][i] = hi;
                ql[s][i] = f2tf(v[i] - __uint_as_float(hi));
            }
        }
    }

    const float* bp_lo = bias + ((size_t)h * SEQ + q0 + row_lo) * SEQ;
    const float* bp_hi = bias + ((size_t)h * SEQ + q0 + row_hi) * SEQ;

    float o[4][4];
    #pragma unroll
    for (int i = 0; i < 4; i++)
        #pragma unroll
        for (int j = 0; j < 4; j++) o[i][j] = 0.0f;
    float l_lo = 0.0f, l_hi = 0.0f;

    for (int kb = 0; kb < SEQ; kb += ABC) {
        __syncthreads();
        {
            const float kf[4] = {kv.x, kv.y, kv.z, kv.w};
            const float vf[4] = {vv.x, vv.y, vv.z, vv.w};
            const int jcol = cmap(jL);
            #pragma unroll
            for (int e = 0; e < 4; e++) {
                const int d = cL * 4 + e;
                Ks[jL][cmap(d)] = f2tf(kf[e]);
                Vts[d][jcol]    = f2tf(vf[e]);
            }
        }
        __syncthreads();

        if (kb + ABC < SEQ) {
            const float* nb = qkv + ((size_t)(b * SEQ + kb + ABC + jL)) * QKV_N + h * 96;
            kv = *(const float4*)(nb + 32 + cL * 4);
            vv = *(const float4*)(nb + 64 + cL * 4);
        }
        float2 blo2[4], bhi2[4];
        #pragma unroll
        for (int ni = 0; ni < 4; ni++) {
            blo2[ni] = *(const float2*)(bp_lo + kb + ni * 8 + 2 * p);
            bhi2[ni] = *(const float2*)(bp_hi + kb + ni * 8 + 2 * p);
        }

        float cf[4][4];
        #pragma unroll
        for (int i = 0; i < 4; i++)
            #pragma unroll
            for (int j = 0; j < 4; j++) cf[i][j] = 0.0f;

        #pragma unroll
        for (int s = 0; s < 4; s++) {
            #pragma unroll
            for (int ni = 0; ni < 4; ni++) {
                const int nr = ni * 8 + mq;
                uint2 bh = *(const uint2*)&Ks[nr][(s * 4 + p) * 2];
                MMA_TF32(cf[ni][0], cf[ni][1], cf[ni][2], cf[ni][3],
                         qh[s][0], qh[s][1], qh[s][2], qh[s][3], bh.x, bh.y);
                MMA_TF32(cf[ni][0], cf[ni][1], cf[ni][2], cf[ni][3],
                         ql[s][0], ql[s][1], ql[s][2], ql[s][3], bh.x, bh.y);
            }
        }

        #pragma unroll
        for (int ni = 0; ni < 4; ni++) {
            float p00 = __expf(cf[ni][0] + blo2[ni].x);
            float p01 = __expf(cf[ni][1] + blo2[ni].y);
            float p10 = __expf(cf[ni][2] + bhi2[ni].x);
            float p11 = __expf(cf[ni][3] + bhi2[ni].y);
            l_lo += p00 + p01;
            l_hi += p10 + p11;
            const int ja = ni * 8 + 2 * p;
            const int ca = cmap(ja);
            const int cb = cmap(ja + 1);
            Ps[row_lo][ca] = f2tf(p00);
            Ps[row_lo][cb] = f2tf(p01);
            Ps[row_hi][ca] = f2tf(p10);
            Ps[row_hi][cb] = f2tf(p11);
        }
        __syncwarp();

        #pragma unroll
        for (int s2 = 0; s2 < 4; s2++) {
            uint2 alo = *(const uint2*)&Ps[row_lo][(s2 * 4 + p) * 2];
            uint2 ahi = *(const uint2*)&Ps[row_hi][(s2 * 4 + p) * 2];
            #pragma unroll
            for (int nt = 0; nt < 4; nt++) {
                uint2 bv = *(const uint2*)&Vts[nt * 8 + mq][(s2 * 4 + p) * 2];
                MMA_TF32(o[nt][0], o[nt][1], o[nt][2], o[nt][3],
                         alo.x, ahi.x, alo.y, ahi.y, bv.x, bv.y);
            }
        }
    }

    #pragma unroll
    for (int m = 1; m <= 2; m <<= 1) {
        l_lo += __shfl_xor_sync(0xffffffffu, l_lo, m);
        l_hi += __shfl_xor_sync(0xffffffffu, l_hi, m);
    }
    const float inv_lo = 1.0f / l_lo;
    const float inv_hi = 1.0f / l_hi;

    float* po_lo = out + ((size_t)(b * SEQ + q0 + row_lo)) * CDIM + h * DHEAD;
    float* po_hi = out + ((size_t)(b * SEQ + q0 + row_hi)) * CDIM + h * DHEAD;
    #pragma unroll
    for (int nt = 0; nt < 4; nt++) {
        float2 w0, w1;
        w0.x = o[nt][0] * inv_lo; w0.y = o[nt][1] * inv_lo;
        w1.x = o[nt][2] * inv_hi; w1.y = o[nt][3] * inv_hi;
        *(float2*)(po_lo + nt * 8 + 2 * p) = w0;
        *(float2*)(po_hi + nt * 8 + 2 * p) = w1;
    }
}

// ---------------------------------------------------------------------------
extern "C" void kernel_launch(void* const* d_in, const int* in_sizes, int n_in,
                              void* d_out, int out_size)
{
    const float* x      = (const float*)d_in[0];  // [B,N,C]
    const float* relpos = (const float*)d_in[1];  // [H,N,N]
    const float* Wqkv   = (const float*)d_in[2];  // [3C,C]
    const float* bqkv   = (const float*)d_in[3];  // [3C]
    const float* Wproj  = (const float*)d_in[4];  // [C,C]
    const float* bproj  = (const float*)d_in[5];  // [C]
    float* out = (float*)d_out;                   // [B,N,C]

    float *qkv = nullptr, *att = nullptr;
    cudaGetSymbolAddress((void**)&qkv, g_qkv);
    cudaGetSymbolAddress((void**)&att, g_att);

    cudaFuncSetAttribute(gemm_tc_kernel,
                         cudaFuncAttributeMaxDynamicSharedMemorySize, GEMM_SMEM);

    // 1) QKV projection
    gemm_tc_kernel<<<dim3(QKV_N / TN, ROWS / TM), 256, GEMM_SMEM>>>(
        x, Wqkv, bqkv, qkv, ROWS, QKV_N, CDIM);

    // 2) tensor-core flash attention
    attn_tc_kernel<<<dim3(BATCH * (SEQ / AQT), HEADS), 256>>>(qkv, relpos, att);

    // 3) output projection
    gemm_tc_kernel<<<dim3(CDIM / TN, ROWS / TM), 256, GEMM_SMEM>>>(
        att, Wproj, bproj, out, ROWS, CDIM, CDIM);
}

// round 10
// speedup vs baseline: 3.4067x; 1.4460x over previous
#include <cuda_runtime.h>
#include <cuda_bf16.h>
#include <cstddef>
#include <cstdint>

// Problem constants
#define BATCH 8
#define SEQ   1024
#define CDIM  768
#define HEADS 24
#define DHEAD 32
#define QKV_N (3*CDIM)          // 2304
#define ROWS  (BATCH*SEQ)       // 8192

__device__ __forceinline__ uint32_t f2tf(float f) {
    uint32_t u; asm("cvt.rna.tf32.f32 %0,%1;" : "=r"(u) : "f"(f)); return u;
}
// RNA-to-tf32 via bit bump (HMMA truncates low 13 bits; +0x1000 -> round-nearest)
__device__ __forceinline__ uint32_t rna(uint32_t u) { return u + 0x1000u; }

#define MMA_TF32(C0,C1,C2,C3, A0,A1,A2,A3, B0,B1) \
    asm("mma.sync.aligned.m16n8k8.row.col.f32.tf32.tf32.f32 " \
        "{%0,%1,%2,%3},{%4,%5,%6,%7},{%8,%9},{%0,%1,%2,%3};" \
        : "+f"(C0), "+f"(C1), "+f"(C2), "+f"(C3) \
        : "r"(A0), "r"(A1), "r"(A2), "r"(A3), "r"(B0), "r"(B1))

__device__ __forceinline__ void ldsm4(uint32_t& r0, uint32_t& r1,
                                      uint32_t& r2, uint32_t& r3, uint32_t addr) {
    asm volatile("ldmatrix.sync.aligned.m8n8.x4.shared.b16 {%0,%1,%2,%3},[%4];"
                 : "=r"(r0), "=r"(r1), "=r"(r2), "=r"(r3) : "r"(addr));
}

#define CP_ASYNC16(dst, src) \
    asm volatile("cp.async.cg.shared.global [%0],[%1],16;" :: "r"(dst), "l"(src))
#define CP_COMMIT() asm volatile("cp.async.commit_group;")
#define CP_WAIT0()  asm volatile("cp.async.wait_group 0;")

// Scratch (allocation-free rule: __device__ globals)
__device__ float g_qkv[(size_t)ROWS * QKV_N];   // [B*N, 2304]
__device__ float g_att[(size_t)ROWS * CDIM];    // [B*N, 768]

// ---------------------------------------------------------------------------
// tf32 tensor-core GEMM with bias (R9, validated — unchanged).
// ---------------------------------------------------------------------------
#define TM 128
#define TN 128
#define TK 32
#define TILE_B (TM * TK * 4)
#define GEMM_SMEM (4 * TILE_B)

__global__ __launch_bounds__(256, 2) void gemm_tc_kernel(
    const float* __restrict__ A, const float* __restrict__ W,
    const float* __restrict__ bias, float* __restrict__ C,
    int M, int N, int K)
{
    extern __shared__ char smem_raw[];
    const uint32_t sb  = (uint32_t)__cvta_generic_to_shared(smem_raw);
    const uint32_t Ab0 = sb;
    const uint32_t Bb0 = sb + 2 * TILE_B;

    const int t    = threadIdx.x;
    const int lane = t & 31;
    const int wid  = t >> 5;
    const int wm   = wid & 3;
    const int wn   = wid >> 2;
    const int m0   = blockIdx.y * TM;
    const int n0   = blockIdx.x * TN;
    const int mq   = lane >> 2;
    const int p    = lane & 3;

    const int rA    = wm * 32 + ((lane >> 3) & 1) * 8 + (lane & 7);
    const int halfA = (lane >> 4) & 1;
    const int xa    = rA & 7;
    const int rB    = wn * 64 + ((lane >> 4) & 1) * 8 + (lane & 7);
    const int halfB = (lane >> 3) & 1;
    const int xb    = rB & 7;

    const int lr = t >> 3;
    const int lc = t & 7;

    float c[2][8][4];
    #pragma unroll
    for (int i = 0; i < 2; i++)
        #pragma unroll
        for (int j = 0; j < 8; j++)
            #pragma unroll
            for (int r = 0; r < 4; r++) c[i][j][r] = 0.0f;

    const int nk = K / TK;

    #pragma unroll
    for (int i = 0; i < 4; i++) {
        const int r = lr + i * 32;
        const uint32_t sw = (uint32_t)((lc ^ (r & 7)) * 16);
        CP_ASYNC16(Ab0 + r * 128 + sw, (const char*)&A[(size_t)(m0 + r) * K + lc * 4]);
        CP_ASYNC16(Bb0 + r * 128 + sw, (const char*)&W[(size_t)(n0 + r) * K + lc * 4]);
    }
    CP_COMMIT();
    CP_WAIT0();
    __syncthreads();

    int buf = 0;
    for (int kt = 0; kt < nk; kt++) {
        const bool more = (kt + 1 < nk);
        if (more) {
            const int ko = (kt + 1) * TK;
            const uint32_t Ad = Ab0 + (buf ^ 1) * TILE_B;
            const uint32_t Bd = Bb0 + (buf ^ 1) * TILE_B;
            #pragma unroll
            for (int i = 0; i < 4; i++) {
                const int r = lr + i * 32;
                const uint32_t sw = (uint32_t)((lc ^ (r & 7)) * 16);
                CP_ASYNC16(Ad + r * 128 + sw, (const char*)&A[(size_t)(m0 + r) * K + ko + lc * 4]);
                CP_ASYNC16(Bd + r * 128 + sw, (const char*)&W[(size_t)(n0 + r) * K + ko + lc * 4]);
            }
            CP_COMMIT();
        }

        const uint32_t Abase = Ab0 + buf * TILE_B;
        const uint32_t Bbase = Bb0 + buf * TILE_B;
        #pragma unroll
        for (int s = 0; s < 4; s++) {
            uint32_t af[2][4];
            #pragma unroll
            for (int mi = 0; mi < 2; mi++) {
                ldsm4(af[mi][0], af[mi][1], af[mi][2], af[mi][3],
                      Abase + (rA + mi * 16) * 128 + ((uint32_t)(((2 * s + halfA) ^ xa) << 4)));
                af[mi][0] = rna(af[mi][0]); af[mi][1] = rna(af[mi][1]);
                af[mi][2] = rna(af[mi][2]); af[mi][3] = rna(af[mi][3]);
            }
            uint32_t bf[8][2];
            #pragma unroll
            for (int g = 0; g < 4; g++) {
                uint32_t r0, r1, r2, r3;
                ldsm4(r0, r1, r2, r3,
                      Bbase + (rB + g * 16) * 128 + ((uint32_t)(((2 * s + halfB) ^ xb) << 4)));
                bf[2 * g][0] = rna(r0); bf[2 * g][1] = rna(r1);
                bf[2 * g + 1][0] = rna(r2); bf[2 * g + 1][1] = rna(r3);
            }
            #pragma unroll
            for (int mi = 0; mi < 2; mi++)
                #pragma unroll
                for (int ni = 0; ni < 8; ni++)
                    MMA_TF32(c[mi][ni][0], c[mi][ni][1], c[mi][ni][2], c[mi][ni][3],
                             af[mi][0], af[mi][1], af[mi][2], af[mi][3],
                             bf[ni][0], bf[ni][1]);
        }

        if (more) CP_WAIT0();
        __syncthreads();
        buf ^= 1;
    }

    #pragma unroll
    for (int ni = 0; ni < 8; ni++) {
        const int n = n0 + wn * 64 + ni * 8 + p * 2;
        const float2 bb = *(const float2*)&bias[n];
        #pragma unroll
        for (int mi = 0; mi < 2; mi++) {
            const int mA = m0 + wm * 32 + mi * 16 + mq;
            float2 w0, w1;
            w0.x = c[mi][ni][0] + bb.x; w0.y = c[mi][ni][1] + bb.y;
            w1.x = c[mi][ni][2] + bb.x; w1.y = c[mi][ni][3] + bb.y;
            *(float2*)&C[(size_t)mA * N + n]       = w0;
            *(float2*)&C[(size_t)(mA + 8) * N + n] = w1;
        }
    }
}

// ---------------------------------------------------------------------------
// Tensor-core flash attention, ldmatrix edition.
// 128 q/block (8 warps x 16), ABC=64 keys/tile.
// K: [64][32]f32 linear 128B rows, 16B-chunk XOR swizzle.
// V^T: [32][64]f32 256B rows, chunk ^ (d&7) swizzle.
// P: [128][64]f32 256B rows, chunk ^ (q&7) swizzle; warp-private rows.
// All operands raw fp32 bits in smem; rna bump after ldmatrix.
// ---------------------------------------------------------------------------
#define AQT 128
#define ABC 64
#define KS_OFF 0
#define VS_OFF 8192
#define PS_OFF 16384
#define ATTN_SMEM 49152

__global__ __launch_bounds__(256, 2) void attn_tc_kernel(
    const float* __restrict__ qkv,   // [B*N, 2304]
    const float* __restrict__ bias,  // [H, N, N]
    float* __restrict__ out)         // [B*N, 768]
{
    extern __shared__ char asmem[];
    const uint32_t sb = (uint32_t)__cvta_generic_to_shared(asmem);

    const int t    = threadIdx.x;
    const int lane = t & 31;
    const int w    = t >> 5;
    const int b    = blockIdx.x >> 3;
    const int qb   = blockIdx.x & 7;
    const int h    = blockIdx.y;
    const int q0   = qb * AQT;
    const int mq   = lane >> 2;
    const int p    = lane & 3;

    const float scale = 0.17677669529663687f;   // 1/sqrt(32)

    const int row_lo = w * 16 + mq;
    const int row_hi = row_lo + 8;

    // ldmatrix lane mappings (validated patterns from the GEMM)
    const int bRow  = ((lane >> 4) & 1) * 8 + (lane & 7);   // B-frag row-in-16
    const int bHalf = (lane >> 3) & 1;
    const int bx    = lane & 7;                              // row&7 for swizzle
    const int aRow  = w * 16 + ((lane >> 3) & 1) * 8 + (lane & 7);  // P A-frag row
    const int aHalf = (lane >> 4) & 1;
    const int ax    = aRow & 7;

    // staging: thread -> key row jL, chunks cLs and cLs+4 (16B each)
    const int jL  = t >> 2;
    const int cLs = t & 3;
    const float* kv0 = qkv + ((size_t)(b * SEQ + jL)) * QKV_N + h * 96;
    float4 kA = *(const float4*)(kv0 + 32 + cLs * 4);
    float4 kB = *(const float4*)(kv0 + 32 + cLs * 4 + 16);
    float4 vA = *(const float4*)(kv0 + 64 + cLs * 4);
    float4 vB = *(const float4*)(kv0 + 64 + cLs * 4 + 16);

    // ---- Q fragments, hi + residual (exact fp32 split) ----
    uint32_t qh[4][4], ql[4][4];
    {
        const float* Qa = qkv + ((size_t)(b * SEQ + q0 + row_lo)) * QKV_N + h * 96;
        const float* Qb = qkv + ((size_t)(b * SEQ + q0 + row_hi)) * QKV_N + h * 96;
        #pragma unroll
        for (int s = 0; s < 4; s++) {
            float v[4];
            v[0] = Qa[s * 8 + p]     * scale;
            v[1] = Qb[s * 8 + p]     * scale;
            v[2] = Qa[s * 8 + p + 4] * scale;
            v[3] = Qb[s * 8 + p + 4] * scale;
            #pragma unroll
            for (int i = 0; i < 4; i++) {
                uint32_t hi = f2tf(v[i]);
                qh[s][i] = hi;
                ql[s][i] = f2tf(v[i] - __uint_as_float(hi));
            }
        }
    }

    const float* bp_lo = bias + ((size_t)h * SEQ + q0 + row_lo) * SEQ;
    const float* bp_hi = bias + ((size_t)h * SEQ + q0 + row_hi) * SEQ;

    float o[4][4];
    #pragma unroll
    for (int i = 0; i < 4; i++)
        #pragma unroll
        for (int j = 0; j < 4; j++) o[i][j] = 0.0f;
    float l_lo = 0.0f, l_hi = 0.0f;

    for (int kb = 0; kb < SEQ; kb += ABC) {
        __syncthreads();   // all readers of previous K/V done
        // ---- store staged K (linear rows) and V^T (transposed) ----
        {
            // K row jL: STS.128 at chunk c ^ (jL&7)
            *(float4*)(asmem + KS_OFF + jL * 128 + ((cLs       ^ (jL & 7)) << 4)) = kA;
            *(float4*)(asmem + KS_OFF + jL * 128 + (((cLs + 4) ^ (jL & 7)) << 4)) = kB;
            // V^T: element (d, jL)
            const float vfA[4] = {vA.x, vA.y, vA.z, vA.w};
            const float vfB[4] = {vB.x, vB.y, vB.z, vB.w};
            #pragma unroll
            for (int e = 0; e < 4; e++) {
                const int d0 = cLs * 4 + e;
                const int d1 = d0 + 16;
                *(float*)(asmem + VS_OFF + d0 * 256 + (((jL >> 2) ^ (d0 & 7)) << 4) + ((jL & 3) << 2)) = vfA[e];
                *(float*)(asmem + VS_OFF + d1 * 256 + (((jL >> 2) ^ (d1 & 7)) << 4) + ((jL & 3) << 2)) = vfB[e];
            }
        }
        __syncthreads();

        // ---- prefetch next tile K/V into regs ----
        if (kb + ABC < SEQ) {
            const float* nb = qkv + ((size_t)(b * SEQ + kb + ABC + jL)) * QKV_N + h * 96;
            kA = *(const float4*)(nb + 32 + cLs * 4);
            kB = *(const float4*)(nb + 32 + cLs * 4 + 16);
            vA = *(const float4*)(nb + 64 + cLs * 4);
            vB = *(const float4*)(nb + 64 + cLs * 4 + 16);
        }

        // ---- QK + softmax numerator, 2 j-tiles (16 keys) per group ----
        #pragma unroll
        for (int g = 0; g < 4; g++) {
            float2 blo2[2], bhi2[2];
            #pragma unroll
            for (int u = 0; u < 2; u++) {
                const int jj = kb + (2 * g + u) * 8 + 2 * p;
                blo2[u] = *(const float2*)(bp_lo + jj);
                bhi2[u] = *(const float2*)(bp_hi + jj);
            }

            float cf[2][4];
            #pragma unroll
            for (int u = 0; u < 2; u++)
                #pragma unroll
                for (int r = 0; r < 4; r++) cf[u][r] = 0.0f;

            #pragma unroll
            for (int s = 0; s < 4; s++) {
                uint32_t r0, r1, r2, r3;
                ldsm4(r0, r1, r2, r3,
                      sb + KS_OFF + (g * 16 + bRow) * 128 +
                      ((uint32_t)(((2 * s + bHalf) ^ bx) << 4)));
                r0 = rna(r0); r1 = rna(r1); r2 = rna(r2); r3 = rna(r3);
                MMA_TF32(cf[0][0], cf[0][1], cf[0][2], cf[0][3],
                         qh[s][0], qh[s][1], qh[s][2], qh[s][3], r0, r1);
                MMA_TF32(cf[0][0], cf[0][1], cf[0][2], cf[0][3],
                         ql[s][0], ql[s][1], ql[s][2], ql[s][3], r0, r1);
                MMA_TF32(cf[1][0], cf[1][1], cf[1][2], cf[1][3],
                         qh[s][0], qh[s][1], qh[s][2], qh[s][3], r2, r3);
                MMA_TF32(cf[1][0], cf[1][1], cf[1][2], cf[1][3],
                         ql[s][0], ql[s][1], ql[s][2], ql[s][3], r2, r3);
            }

            #pragma unroll
            for (int u = 0; u < 2; u++) {
                const int ni = 2 * g + u;
                const float p00 = __expf(cf[u][0] + blo2[u].x);
                const float p01 = __expf(cf[u][1] + blo2[u].y);
                const float p10 = __expf(cf[u][2] + bhi2[u].x);
                const float p11 = __expf(cf[u][3] + bhi2[u].y);
                l_lo += p00 + p01;
                l_hi += p10 + p11;
                const int c  = 2 * ni + (p >> 1);
                const int ob = (p & 1) << 3;
                *(float2*)(asmem + PS_OFF + row_lo * 256 + ((c ^ (row_lo & 7)) << 4) + ob)
                    = make_float2(p00, p01);
                *(float2*)(asmem + PS_OFF + row_hi * 256 + ((c ^ (row_hi & 7)) << 4) + ob)
                    = make_float2(p10, p11);
            }
        }
        __syncwarp();   // P rows are warp-private

        // ---- O += P V ----
        #pragma unroll
        for (int s2 = 0; s2 < 8; s2++) {
            uint32_t a0, a1, a2, a3;
            ldsm4(a0, a1, a2, a3,
                  sb + PS_OFF + aRow * 256 +
                  ((uint32_t)(((2 * s2 + aHalf) ^ ax) << 4)));
            a0 = rna(a0); a1 = rna(a1); a2 = rna(a2); a3 = rna(a3);
            #pragma unroll
            for (int grp = 0; grp < 2; grp++) {
                uint32_t v0, v1, v2, v3;
                ldsm4(v0, v1, v2, v3,
                      sb + VS_OFF + (grp * 16 + bRow) * 256 +
                      ((uint32_t)(((2 * s2 + bHalf) ^ bx) << 4)));
                v0 = rna(v0); v1 = rna(v1); v2 = rna(v2); v3 = rna(v3);
                MMA_TF32(o[grp * 2][0], o[grp * 2][1], o[grp * 2][2], o[grp * 2][3],
                         a0, a1, a2, a3, v0, v1);
                MMA_TF32(o[grp * 2 + 1][0], o[grp * 2 + 1][1],
                         o[grp * 2 + 1][2], o[grp * 2 + 1][3],
                         a0, a1, a2, a3, v2, v3);
            }
        }
    }

    // ---- row-sum reduce across the 4 p-lanes of each row quad ----
    #pragma unroll
    for (int m = 1; m <= 2; m <<= 1) {
        l_lo += __shfl_xor_sync(0xffffffffu, l_lo, m);
        l_hi += __shfl_xor_sync(0xffffffffu, l_hi, m);
    }
    const float inv_lo = 1.0f / l_lo;
    const float inv_hi = 1.0f / l_hi;

    float* po_lo = out + ((size_t)(b * SEQ + q0 + row_lo)) * CDIM + h * DHEAD;
    float* po_hi = out + ((size_t)(b * SEQ + q0 + row_hi)) * CDIM + h * DHEAD;
    #pragma unroll
    for (int nt = 0; nt < 4; nt++) {
        float2 w0, w1;
        w0.x = o[nt][0] * inv_lo; w0.y = o[nt][1] * inv_lo;
        w1.x = o[nt][2] * inv_hi; w1.y = o[nt][3] * inv_hi;
        *(float2*)(po_lo + nt * 8 + 2 * p) = w0;
        *(float2*)(po_hi + nt * 8 + 2 * p) = w1;
    }
}

// ---------------------------------------------------------------------------
extern "C" void kernel_launch(void* const* d_in, const int* in_sizes, int n_in,
                              void* d_out, int out_size)
{
    const float* x      = (const float*)d_in[0];  // [B,N,C]
    const float* relpos = (const float*)d_in[1];  // [H,N,N]
    const float* Wqkv   = (const float*)d_in[2];  // [3C,C]
    const float* bqkv   = (const float*)d_in[3];  // [3C]
    const float* Wproj  = (const float*)d_in[4];  // [C,C]
    const float* bproj  = (const float*)d_in[5];  // [C]
    float* out = (float*)d_out;                   // [B,N,C]

    float *qkv = nullptr, *att = nullptr;
    cudaGetSymbolAddress((void**)&qkv, g_qkv);
    cudaGetSymbolAddress((void**)&att, g_att);

    cudaFuncSetAttribute(gemm_tc_kernel,
                         cudaFuncAttributeMaxDynamicSharedMemorySize, GEMM_SMEM);
    cudaFuncSetAttribute(attn_tc_kernel,
                         cudaFuncAttributeMaxDynamicSharedMemorySize, ATTN_SMEM);

    // 1) QKV projection
    gemm_tc_kernel<<<dim3(QKV_N / TN, ROWS / TM), 256, GEMM_SMEM>>>(
        x, Wqkv, bqkv, qkv, ROWS, QKV_N, CDIM);

    // 2) tensor-core flash attention
    attn_tc_kernel<<<dim3(BATCH * (SEQ / AQT), HEADS), 256, ATTN_SMEM>>>(
        qkv, relpos, att);

    // 3) output projection
    gemm_tc_kernel<<<dim3(CDIM / TN, ROWS / TM), 256, GEMM_SMEM>>>(
        att, Wproj, bproj, out, ROWS, CDIM, CDIM);
}